// round 9
// baseline (speedup 1.0000x reference)
#include <cuda_runtime.h>
#include <cuda_bf16.h>
#include <math.h>
#include <stdint.h>

#define BATCH   2
#define S_LEN   2048
#define EMB     1024
#define HEADS   16
#define HD      64
#define NEG_VAL 100000.0f
#define MTOT    (BATCH * S_LEN)      // 4096

typedef unsigned short ush;

// ---------------------------------------------------------------------------
// Scratch (device globals; no runtime allocation allowed).
// ---------------------------------------------------------------------------
__device__ __align__(256) ush g_xhi[(size_t)MTOT * EMB];
__device__ __align__(256) ush g_xlo[(size_t)MTOT * EMB];
__device__ __align__(256) ush g_wah[(size_t)(3 * EMB) * EMB];
__device__ __align__(256) ush g_wal[(size_t)(3 * EMB) * EMB];
__device__ __align__(256) ush g_wph[(size_t)EMB * EMB];
__device__ __align__(256) ush g_wpl[(size_t)EMB * EMB];
__device__ __align__(256) ush g_athi[(size_t)MTOT * EMB];
__device__ __align__(256) ush g_atlo[(size_t)MTOT * EMB];
// Per-head split Q/K/V: [b][h][s][d]
__device__ __align__(256) ush g_qh[(size_t)MTOT * EMB];
__device__ __align__(256) ush g_ql[(size_t)MTOT * EMB];
__device__ __align__(256) ush g_kh[(size_t)MTOT * EMB];
__device__ __align__(256) ush g_kl[(size_t)MTOT * EMB];
__device__ __align__(256) ush g_vh[(size_t)MTOT * EMB];
__device__ __align__(256) ush g_vl[(size_t)MTOT * EMB];

// ---------------------------------------------------------------------------
// Helpers
// ---------------------------------------------------------------------------
__device__ __forceinline__ uint32_t smem_to_u32(const void* p) {
    uint32_t a;
    asm("{ .reg .u64 t; cvta.to.shared.u64 t, %1; cvt.u32.u64 %0, t; }" : "=r"(a) : "l"(p));
    return a;
}

#define CP_ASYNC16(dst, src) \
    asm volatile("cp.async.cg.shared.global [%0], [%1], 16;" :: "r"(dst), "l"(src))
#define CP_COMMIT() asm volatile("cp.async.commit_group;")
#define CP_WAIT1()  asm volatile("cp.async.wait_group 1;")
#define CP_WAIT0()  asm volatile("cp.async.wait_group 0;")

#define LDMX4(r0, r1, r2, r3, addr) \
    asm volatile("ldmatrix.sync.aligned.m8n8.x4.shared.b16 {%0,%1,%2,%3}, [%4];" \
                 : "=r"(r0), "=r"(r1), "=r"(r2), "=r"(r3) : "r"(addr))
#define LDMX4T(r0, r1, r2, r3, addr) \
    asm volatile("ldmatrix.sync.aligned.m8n8.x4.trans.shared.b16 {%0,%1,%2,%3}, [%4];" \
                 : "=r"(r0), "=r"(r1), "=r"(r2), "=r"(r3) : "r"(addr))

__device__ __forceinline__ void mma_bf16(float* d, const uint32_t* a, const uint32_t* b)
{
    asm volatile(
        "mma.sync.aligned.m16n8k16.row.col.f32.bf16.bf16.f32 "
        "{%0,%1,%2,%3}, {%4,%5,%6,%7}, {%8,%9}, {%0,%1,%2,%3};"
        : "+f"(d[0]), "+f"(d[1]), "+f"(d[2]), "+f"(d[3])
        : "r"(a[0]), "r"(a[1]), "r"(a[2]), "r"(a[3]), "r"(b[0]), "r"(b[1]));
}

// hi split via mantissa truncation (exact residual), pack two hi-bf16
__device__ __forceinline__ uint32_t pack_hi(float e, float o) {
    uint32_t r;
    asm("prmt.b32 %0, %1, %2, 0x7632;" : "=r"(r)
        : "r"(__float_as_uint(e)), "r"(__float_as_uint(o)));
    return r;
}
__device__ __forceinline__ uint32_t pack_lo(float e, float o) {
    float le = e - __uint_as_float(__float_as_uint(e) & 0xFFFF0000u);
    float lo = o - __uint_as_float(__float_as_uint(o) & 0xFFFF0000u);
    uint32_t r;
    asm("cvt.rn.bf16x2.f32 %0, %1, %2;" : "=r"(r) : "f"(lo), "f"(le));
    return r;
}

// ---------------------------------------------------------------------------
// fp32 -> bf16 hi/lo split (GEMM operand prep)
// ---------------------------------------------------------------------------
__global__ void convert_split(const float* __restrict__ in,
                              ush* __restrict__ hi, ush* __restrict__ lo, int n)
{
    int i = blockIdx.x * blockDim.x + threadIdx.x;
    if (i < n) {
        float v = in[i];
        __nv_bfloat16 h = __float2bfloat16(v);
        __nv_bfloat16 l = __float2bfloat16(v - __bfloat162float(h));
        hi[i] = *(ush*)&h;
        lo[i] = *(ush*)&l;
    }
}

__global__ void convert_transpose(const float* __restrict__ W,
                                  ush* __restrict__ hi, ush* __restrict__ lo,
                                  int K, int N)
{
    __shared__ float t[32][33];
    int n0 = blockIdx.x * 32, k0 = blockIdx.y * 32;
    int tx = threadIdx.x, ty = threadIdx.y;
#pragma unroll
    for (int i = 0; i < 4; i++)
        t[ty + i * 8][tx] = W[(size_t)(k0 + ty + i * 8) * N + n0 + tx];
    __syncthreads();
#pragma unroll
    for (int i = 0; i < 4; i++) {
        float v = t[tx][ty + i * 8];
        __nv_bfloat16 h = __float2bfloat16(v);
        __nv_bfloat16 l = __float2bfloat16(v - __bfloat162float(h));
        size_t o = (size_t)(n0 + ty + i * 8) * K + k0 + tx;
        hi[o] = *(ush*)&h;
        lo[o] = *(ush*)&l;
    }
}

// ---------------------------------------------------------------------------
// GEMM mainloop constants (128x128 tile, BK=32, 2-stage cp.async)
// ---------------------------------------------------------------------------
#define TROW      80
#define TILE_B    (128 * TROW)
#define STAGE_B   (4 * TILE_B)
#define GEMM_SMEM (2 * STAGE_B)          // 81920 -> 2 CTAs/SM

// ---------------------------------------------------------------------------
// Generic split-bf16 GEMM with fp32+bias output (used for proj)
// ---------------------------------------------------------------------------
__global__ __launch_bounds__(256, 2) void gemm_mma_split(
    const ush* __restrict__ Ahi, const ush* __restrict__ Alo,
    const ush* __restrict__ Bhi, const ush* __restrict__ Blo,
    const float* __restrict__ bias, float* __restrict__ C,
    int M, int N, int K)
{
    extern __shared__ char smem[];
    const uint32_t sb0 = smem_to_u32(smem);
    const int tid = threadIdx.x;
    const int wid = tid >> 5;
    const int l   = tid & 31;
    const int bx = blockIdx.x;
    const int by = blockIdx.y;
    const int wm = wid >> 2;
    const int wn = wid & 3;

    int r0 = tid >> 2,         cc0 = tid & 3;
    int r1 = (tid + 256) >> 2, cc1 = tid & 3;
    uint32_t so0 = (uint32_t)r0 * TROW + cc0 * 16;
    uint32_t so1 = (uint32_t)r1 * TROW + cc1 * 16;
    size_t ga0 = (size_t)(by * 128 + r0) * K + cc0 * 8;
    size_t ga1 = (size_t)(by * 128 + r1) * K + cc1 * 8;
    size_t gb0 = (size_t)(bx * 128 + r0) * K + cc0 * 8;
    size_t gb1 = (size_t)(bx * 128 + r1) * K + cc1 * 8;

    const int NT = K / 32;

    auto issue = [&](int kt) {
        uint32_t sb = sb0 + (uint32_t)(kt & 1) * STAGE_B;
        size_t ko = (size_t)kt * 32;
        CP_ASYNC16(sb + 0 * TILE_B + so0, Ahi + ga0 + ko);
        CP_ASYNC16(sb + 0 * TILE_B + so1, Ahi + ga1 + ko);
        CP_ASYNC16(sb + 1 * TILE_B + so0, Alo + ga0 + ko);
        CP_ASYNC16(sb + 1 * TILE_B + so1, Alo + ga1 + ko);
        CP_ASYNC16(sb + 2 * TILE_B + so0, Bhi + gb0 + ko);
        CP_ASYNC16(sb + 2 * TILE_B + so1, Bhi + gb1 + ko);
        CP_ASYNC16(sb + 3 * TILE_B + so0, Blo + gb0 + ko);
        CP_ASYNC16(sb + 3 * TILE_B + so1, Blo + gb1 + ko);
        CP_COMMIT();
    };

    float acc[4][4][4];
#pragma unroll
    for (int mi = 0; mi < 4; mi++)
#pragma unroll
        for (int j = 0; j < 4; j++)
#pragma unroll
            for (int e = 0; e < 4; e++) acc[mi][j][e] = 0.0f;

    const uint32_t a_lane = (uint32_t)(wm * 64 + (l & 15)) * TROW + (l >> 4) * 16;
    const uint32_t b_lane = (uint32_t)(wn * 32 + (l & 7) + ((l >> 4) * 8)) * TROW
                          + ((l >> 3) & 1) * 16;

    issue(0);

    for (int kt = 0; kt < NT; kt++) {
        if (kt + 1 < NT) { issue(kt + 1); CP_WAIT1(); }
        else             { CP_WAIT0(); }
        __syncthreads();

        uint32_t sb = sb0 + (uint32_t)(kt & 1) * STAGE_B;

#pragma unroll
        for (int ks8 = 0; ks8 < 2; ks8++) {
            const uint32_t ko = ks8 * 32;
            uint32_t ah[4][4], al[4][4], bh[2][4], bl[2][4];
#pragma unroll
            for (int mi = 0; mi < 4; mi++) {
                uint32_t ad = sb + a_lane + mi * (16 * TROW) + ko;
                LDMX4(ah[mi][0], ah[mi][1], ah[mi][2], ah[mi][3], ad);
                LDMX4(al[mi][0], al[mi][1], al[mi][2], al[mi][3], ad + TILE_B);
            }
#pragma unroll
            for (int nb = 0; nb < 2; nb++) {
                uint32_t bd = sb + 2 * TILE_B + b_lane + nb * (16 * TROW) + ko;
                LDMX4(bh[nb][0], bh[nb][1], bh[nb][2], bh[nb][3], bd);
                LDMX4(bl[nb][0], bl[nb][1], bl[nb][2], bl[nb][3], bd + TILE_B);
            }
#pragma unroll
            for (int mi = 0; mi < 4; mi++)
#pragma unroll
                for (int j = 0; j < 4; j++)
                    mma_bf16(acc[mi][j], ah[mi], &bh[j >> 1][(j & 1) * 2]);
#pragma unroll
            for (int mi = 0; mi < 4; mi++)
#pragma unroll
                for (int j = 0; j < 4; j++)
                    mma_bf16(acc[mi][j], ah[mi], &bl[j >> 1][(j & 1) * 2]);
#pragma unroll
            for (int mi = 0; mi < 4; mi++)
#pragma unroll
                for (int j = 0; j < 4; j++)
                    mma_bf16(acc[mi][j], al[mi], &bh[j >> 1][(j & 1) * 2]);
        }
        __syncthreads();
    }

#pragma unroll
    for (int mi = 0; mi < 4; mi++) {
        int row = by * 128 + wm * 64 + mi * 16 + (l >> 2);
#pragma unroll
        for (int j = 0; j < 4; j++) {
            int col = bx * 128 + wn * 32 + j * 8 + (l & 3) * 2;
            float b0 = bias[col], b1 = bias[col + 1];
            float2 v0 = make_float2(acc[mi][j][0] + b0, acc[mi][j][1] + b1);
            float2 v1 = make_float2(acc[mi][j][2] + b0, acc[mi][j][3] + b1);
            *(float2*)(C + (size_t)row * N + col)       = v0;
            *(float2*)(C + (size_t)(row + 8) * N + col) = v1;
        }
    }
}

// ---------------------------------------------------------------------------
// QKV GEMM with fused per-head hi/lo split epilogue.
// N=3072, K=1024. col -> head h = col/192, section q/k/v = (col%192)/64.
// Q pre-scaled by 1/8 (exact power of two). Output: g_{q,k,v}{h,l}[b][h][s][d].
// ---------------------------------------------------------------------------
__global__ __launch_bounds__(256, 2) void gemm_qkv_split(
    const ush* __restrict__ Ahi, const ush* __restrict__ Alo,
    const ush* __restrict__ Bhi, const ush* __restrict__ Blo,
    const float* __restrict__ bias)
{
    const int K = EMB;
    extern __shared__ char smem[];
    const uint32_t sb0 = smem_to_u32(smem);
    const int tid = threadIdx.x;
    const int wid = tid >> 5;
    const int l   = tid & 31;
    const int bx = blockIdx.x;
    const int by = blockIdx.y;
    const int wm = wid >> 2;
    const int wn = wid & 3;

    int r0 = tid >> 2,         cc0 = tid & 3;
    int r1 = (tid + 256) >> 2, cc1 = tid & 3;
    uint32_t so0 = (uint32_t)r0 * TROW + cc0 * 16;
    uint32_t so1 = (uint32_t)r1 * TROW + cc1 * 16;
    size_t ga0 = (size_t)(by * 128 + r0) * K + cc0 * 8;
    size_t ga1 = (size_t)(by * 128 + r1) * K + cc1 * 8;
    size_t gb0 = (size_t)(bx * 128 + r0) * K + cc0 * 8;
    size_t gb1 = (size_t)(bx * 128 + r1) * K + cc1 * 8;

    const int NT = K / 32;

    auto issue = [&](int kt) {
        uint32_t sb = sb0 + (uint32_t)(kt & 1) * STAGE_B;
        size_t ko = (size_t)kt * 32;
        CP_ASYNC16(sb + 0 * TILE_B + so0, Ahi + ga0 + ko);
        CP_ASYNC16(sb + 0 * TILE_B + so1, Ahi + ga1 + ko);
        CP_ASYNC16(sb + 1 * TILE_B + so0, Alo + ga0 + ko);
        CP_ASYNC16(sb + 1 * TILE_B + so1, Alo + ga1 + ko);
        CP_ASYNC16(sb + 2 * TILE_B + so0, Bhi + gb0 + ko);
        CP_ASYNC16(sb + 2 * TILE_B + so1, Bhi + gb1 + ko);
        CP_ASYNC16(sb + 3 * TILE_B + so0, Blo + gb0 + ko);
        CP_ASYNC16(sb + 3 * TILE_B + so1, Blo + gb1 + ko);
        CP_COMMIT();
    };

    float acc[4][4][4];
#pragma unroll
    for (int mi = 0; mi < 4; mi++)
#pragma unroll
        for (int j = 0; j < 4; j++)
#pragma unroll
            for (int e = 0; e < 4; e++) acc[mi][j][e] = 0.0f;

    const uint32_t a_lane = (uint32_t)(wm * 64 + (l & 15)) * TROW + (l >> 4) * 16;
    const uint32_t b_lane = (uint32_t)(wn * 32 + (l & 7) + ((l >> 4) * 8)) * TROW
                          + ((l >> 3) & 1) * 16;

    issue(0);

    for (int kt = 0; kt < NT; kt++) {
        if (kt + 1 < NT) { issue(kt + 1); CP_WAIT1(); }
        else             { CP_WAIT0(); }
        __syncthreads();

        uint32_t sb = sb0 + (uint32_t)(kt & 1) * STAGE_B;

#pragma unroll
        for (int ks8 = 0; ks8 < 2; ks8++) {
            const uint32_t ko = ks8 * 32;
            uint32_t ah[4][4], al[4][4], bh[2][4], bl[2][4];
#pragma unroll
            for (int mi = 0; mi < 4; mi++) {
                uint32_t ad = sb + a_lane + mi * (16 * TROW) + ko;
                LDMX4(ah[mi][0], ah[mi][1], ah[mi][2], ah[mi][3], ad);
                LDMX4(al[mi][0], al[mi][1], al[mi][2], al[mi][3], ad + TILE_B);
            }
#pragma unroll
            for (int nb = 0; nb < 2; nb++) {
                uint32_t bd = sb + 2 * TILE_B + b_lane + nb * (16 * TROW) + ko;
                LDMX4(bh[nb][0], bh[nb][1], bh[nb][2], bh[nb][3], bd);
                LDMX4(bl[nb][0], bl[nb][1], bl[nb][2], bl[nb][3], bd + TILE_B);
            }
#pragma unroll
            for (int mi = 0; mi < 4; mi++)
#pragma unroll
                for (int j = 0; j < 4; j++)
                    mma_bf16(acc[mi][j], ah[mi], &bh[j >> 1][(j & 1) * 2]);
#pragma unroll
            for (int mi = 0; mi < 4; mi++)
#pragma unroll
                for (int j = 0; j < 4; j++)
                    mma_bf16(acc[mi][j], ah[mi], &bl[j >> 1][(j & 1) * 2]);
#pragma unroll
            for (int mi = 0; mi < 4; mi++)
#pragma unroll
                for (int j = 0; j < 4; j++)
                    mma_bf16(acc[mi][j], al[mi], &bh[j >> 1][(j & 1) * 2]);
        }
        __syncthreads();
    }

    // Fused epilogue: bias, route to per-head q/k/v, scale q by 1/8, split hi/lo.
#pragma unroll
    for (int mi = 0; mi < 4; mi++) {
        int row = by * 128 + wm * 64 + mi * 16 + (l >> 2);
        int b_ = row >> 11;          // / S_LEN
        int s  = row & (S_LEN - 1);
#pragma unroll
        for (int j = 0; j < 4; j++) {
            int col = bx * 128 + wn * 32 + j * 8 + (l & 3) * 2;
            float bb0 = bias[col], bb1 = bias[col + 1];
            float v0 = acc[mi][j][0] + bb0, v1 = acc[mi][j][1] + bb1;
            float v2 = acc[mi][j][2] + bb0, v3 = acc[mi][j][3] + bb1;

            int h  = col / 192;
            int w_ = col - h * 192;
            uint32_t *dh, *dl;
            int d;
            if (w_ < 64)       { dh = (uint32_t*)g_qh; dl = (uint32_t*)g_ql; d = w_;
                                 v0 *= 0.125f; v1 *= 0.125f; v2 *= 0.125f; v3 *= 0.125f; }
            else if (w_ < 128) { dh = (uint32_t*)g_kh; dl = (uint32_t*)g_kl; d = w_ - 64; }
            else               { dh = (uint32_t*)g_vh; dl = (uint32_t*)g_vl; d = w_ - 128; }

            size_t hb = ((size_t)(b_ * HEADS + h)) * S_LEN;
            size_t i0 = ((hb + s) * HD + d) >> 1;
            size_t i1 = ((hb + s + 8) * HD + d) >> 1;
            dh[i0] = pack_hi(v0, v1);  dl[i0] = pack_lo(v0, v1);
            dh[i1] = pack_hi(v2, v3);  dl[i1] = pack_lo(v2, v3);
        }
    }
}

// ---------------------------------------------------------------------------
// Flash attention, split-bf16 mma.sync. KV tiles 64 rows -> smem 110592 B
// -> 2 CTAs/SM (co-resident CTA fills softmax bubbles in the tensor pipe).
// ---------------------------------------------------------------------------
#define AROW     144
#define AQTILE   (128 * AROW)            // 18432 (Q: 128 rows)
#define KTILE    (64 * AROW)             // 9216  (K/V: 64 rows)
#define AQ_H     0
#define AQ_L     AQTILE
#define ASTG     (2 * AQTILE)            // 36864
#define ASTG_SZ  (4 * KTILE)             // 36864 (Kh,Kl,Vh,Vl)
#define ATT_SMEM (ASTG + 2 * ASTG_SZ)    // 110592

__global__ __launch_bounds__(256, 2) void attn_mma(
    const ush* __restrict__ Qh, const ush* __restrict__ Ql,
    const ush* __restrict__ Kh, const ush* __restrict__ Kl,
    const ush* __restrict__ Vh, const ush* __restrict__ Vl,
    ush* __restrict__ Ohi, ush* __restrict__ Olo)
{
    extern __shared__ char smem[];
    const uint32_t sb = smem_to_u32(smem);
    const int tid = threadIdx.x;
    const int w = tid >> 5;
    const int l = tid & 31;
    const int qt = (int)gridDim.x - 1 - (int)blockIdx.x;    // big tiles first
    const int h = blockIdx.y;
    const int b = blockIdx.z;
    const int qbase = qt * 128;

    const size_t headoff = (size_t)(b * HEADS + h) * S_LEN * HD;

    // KV tile 64x64 bf16 = 512 16B-chunks; 2 per thread
    auto issue_kv = [&](int kt) {
        uint32_t st = sb + ASTG + (uint32_t)(kt & 1) * ASTG_SZ;
        size_t gb = headoff + (size_t)kt * 64 * HD;
#pragma unroll
        for (int j = 0; j < 2; j++) {
            int c = tid + j * 256;
            int r = c >> 3;
            uint32_t dso = (uint32_t)r * AROW + (c & 7) * 16;
            size_t gso = gb + (size_t)r * HD + (c & 7) * 8;
            CP_ASYNC16(st + 0 * KTILE + dso, Kh + gso);
            CP_ASYNC16(st + 1 * KTILE + dso, Kl + gso);
            CP_ASYNC16(st + 2 * KTILE + dso, Vh + gso);
            CP_ASYNC16(st + 3 * KTILE + dso, Vl + gso);
        }
        CP_COMMIT();
    };

    // prologue: Q (128 rows, 4 chunks/thread) + KV stage 0
    {
        size_t gb = headoff + (size_t)qbase * HD;
#pragma unroll
        for (int j = 0; j < 4; j++) {
            int c = tid + j * 256;
            int r = c >> 3;
            uint32_t dso = (uint32_t)r * AROW + (c & 7) * 16;
            size_t gso = gb + (size_t)r * HD + (c & 7) * 8;
            CP_ASYNC16(sb + AQ_H + dso, Qh + gso);
            CP_ASYNC16(sb + AQ_L + dso, Ql + gso);
        }
        uint32_t st = sb + ASTG;
#pragma unroll
        for (int j = 0; j < 2; j++) {
            int c = tid + j * 256;
            int r = c >> 3;
            uint32_t dso = (uint32_t)r * AROW + (c & 7) * 16;
            size_t kso = headoff + (size_t)r * HD + (c & 7) * 8;
            CP_ASYNC16(st + 0 * KTILE + dso, Kh + kso);
            CP_ASYNC16(st + 1 * KTILE + dso, Kl + kso);
            CP_ASYNC16(st + 2 * KTILE + dso, Vh + kso);
            CP_ASYNC16(st + 3 * KTILE + dso, Vl + kso);
        }
        CP_COMMIT();
    }

    // fragment lane addressing
    const uint32_t aq_lane = (uint32_t)(w * 16 + (l & 15)) * AROW + (l >> 4) * 16;
    const uint32_t kb_lane = (uint32_t)((l & 7) + ((l >> 4) * 8)) * AROW + ((l >> 3) & 1) * 16;
    const uint32_t v_lane  = (uint32_t)((l & 7) + ((l >> 3) & 1) * 8) * AROW + ((l >> 4) & 1) * 16;

    float oacc[8][4];
#pragma unroll
    for (int i = 0; i < 8; i++)
#pragma unroll
        for (int e = 0; e < 4; e++) oacc[i][e] = 0.0f;
    float rm0 = -INFINITY, rm1 = -INFINITY, rl0 = 0.0f, rl1 = 0.0f;

    const int row0 = qbase + w * 16 + (l >> 2);   // global q row for accum elems 0,1

    const int nkt = 2 * qt + 2;                   // 64-row kv tiles
    for (int kt = 0; kt < nkt; kt++) {
        if (kt + 1 < nkt) { issue_kv(kt + 1); CP_WAIT1(); }
        else              { CP_WAIT0(); }
        __syncthreads();

        const uint32_t st = sb + ASTG + (uint32_t)(kt & 1) * ASTG_SZ;

        // ---- scores: S = Q @ K^T (3 passes) ----
        float sacc[8][4];
#pragma unroll
        for (int nt = 0; nt < 8; nt++)
#pragma unroll
            for (int e = 0; e < 4; e++) sacc[nt][e] = 0.0f;

#pragma unroll
        for (int ks = 0; ks < 4; ks++) {
            const uint32_t ko = ks * 32;
            uint32_t qhf[4], qlf[4];
            LDMX4(qhf[0], qhf[1], qhf[2], qhf[3], sb + AQ_H + aq_lane + ko);
            LDMX4(qlf[0], qlf[1], qlf[2], qlf[3], sb + AQ_L + aq_lane + ko);
#pragma unroll
            for (int nt2 = 0; nt2 < 4; nt2++) {
                uint32_t khf[4], klf[4];
                uint32_t kd = st + kb_lane + nt2 * (16 * AROW) + ko;
                LDMX4(khf[0], khf[1], khf[2], khf[3], kd);
                LDMX4(klf[0], klf[1], klf[2], klf[3], kd + KTILE);
                mma_bf16(sacc[2 * nt2],     qhf, &khf[0]);
                mma_bf16(sacc[2 * nt2 + 1], qhf, &khf[2]);
                mma_bf16(sacc[2 * nt2],     qhf, &klf[0]);
                mma_bf16(sacc[2 * nt2 + 1], qhf, &klf[2]);
                mma_bf16(sacc[2 * nt2],     qlf, &khf[0]);
                mma_bf16(sacc[2 * nt2 + 1], qlf, &khf[2]);
            }
        }

        // ---- causal mask (only the last two kv tiles can cross the diag) ----
        if (kt >= 2 * qt) {
            const int cb = kt * 64 + (l & 3) * 2;
#pragma unroll
            for (int nt = 0; nt < 8; nt++) {
                int c = cb + nt * 8;
                if (c     > row0)     sacc[nt][0] = -NEG_VAL;
                if (c + 1 > row0)     sacc[nt][1] = -NEG_VAL;
                if (c     > row0 + 8) sacc[nt][2] = -NEG_VAL;
                if (c + 1 > row0 + 8) sacc[nt][3] = -NEG_VAL;
            }
        }

        // ---- online softmax (warp-local; rows live in quads) ----
        float mx0 = -INFINITY, mx1 = -INFINITY;
#pragma unroll
        for (int nt = 0; nt < 8; nt++) {
            mx0 = fmaxf(mx0, fmaxf(sacc[nt][0], sacc[nt][1]));
            mx1 = fmaxf(mx1, fmaxf(sacc[nt][2], sacc[nt][3]));
        }
        mx0 = fmaxf(mx0, __shfl_xor_sync(0xffffffffu, mx0, 1));
        mx0 = fmaxf(mx0, __shfl_xor_sync(0xffffffffu, mx0, 2));
        mx1 = fmaxf(mx1, __shfl_xor_sync(0xffffffffu, mx1, 1));
        mx1 = fmaxf(mx1, __shfl_xor_sync(0xffffffffu, mx1, 2));
        const float mn0 = fmaxf(rm0, mx0), mn1 = fmaxf(rm1, mx1);
        const float f0 = __expf(rm0 - mn0), f1 = __expf(rm1 - mn1);

        float s0 = 0.0f, s1 = 0.0f;
#pragma unroll
        for (int nt = 0; nt < 8; nt++) {
            float p0 = __expf(sacc[nt][0] - mn0);
            float p1 = __expf(sacc[nt][1] - mn0);
            float p2 = __expf(sacc[nt][2] - mn1);
            float p3 = __expf(sacc[nt][3] - mn1);
            sacc[nt][0] = p0; sacc[nt][1] = p1; sacc[nt][2] = p2; sacc[nt][3] = p3;
            s0 += p0 + p1; s1 += p2 + p3;
        }
        s0 += __shfl_xor_sync(0xffffffffu, s0, 1);
        s0 += __shfl_xor_sync(0xffffffffu, s0, 2);
        s1 += __shfl_xor_sync(0xffffffffu, s1, 1);
        s1 += __shfl_xor_sync(0xffffffffu, s1, 2);
        rl0 = rl0 * f0 + s0; rl1 = rl1 * f1 + s1;
        rm0 = mn0; rm1 = mn1;

#pragma unroll
        for (int i = 0; i < 8; i++) {
            oacc[i][0] *= f0; oacc[i][1] *= f0;
            oacc[i][2] *= f1; oacc[i][3] *= f1;
        }

        // ---- O += P @ V (3 passes, P converted in-register) ----
#pragma unroll
        for (int ks2 = 0; ks2 < 4; ks2++) {
            uint32_t aph[4], apl[4];
            float* p0 = sacc[2 * ks2];
            float* p1 = sacc[2 * ks2 + 1];
            aph[0] = pack_hi(p0[0], p0[1]);  apl[0] = pack_lo(p0[0], p0[1]);
            aph[1] = pack_hi(p0[2], p0[3]);  apl[1] = pack_lo(p0[2], p0[3]);
            aph[2] = pack_hi(p1[0], p1[1]);  apl[2] = pack_lo(p1[0], p1[1]);
            aph[3] = pack_hi(p1[2], p1[3]);  apl[3] = pack_lo(p1[2], p1[3]);

            const uint32_t kro = ks2 * (16 * AROW);
#pragma unroll
            for (int dv = 0; dv < 4; dv++) {
                uint32_t vhf[4], vlf[4];
                uint32_t va = st + 2 * KTILE + v_lane + kro + dv * 32;
                LDMX4T(vhf[0], vhf[1], vhf[2], vhf[3], va);
                LDMX4T(vlf[0], vlf[1], vlf[2], vlf[3], va + KTILE);
                mma_bf16(oacc[dv * 2],     aph, &vhf[0]);
                mma_bf16(oacc[dv * 2 + 1], aph, &vhf[2]);
                mma_bf16(oacc[dv * 2],     aph, &vlf[0]);
                mma_bf16(oacc[dv * 2 + 1], aph, &vlf[2]);
                mma_bf16(oacc[dv * 2],     apl, &vhf[0]);
                mma_bf16(oacc[dv * 2 + 1], apl, &vhf[2]);
            }
        }
        __syncthreads();
    }

    // ---- normalize, split, store merged-head layout ----
    const float i0 = 1.0f / rl0, i1 = 1.0f / rl1;
    const size_t grow0 = (size_t)(b * S_LEN + row0) * EMB;
#pragma unroll
    for (int nt8 = 0; nt8 < 8; nt8++) {
        int col = h * HD + nt8 * 8 + (l & 3) * 2;
        float v0 = oacc[nt8][0] * i0, v1 = oacc[nt8][1] * i0;
        float v2 = oacc[nt8][2] * i1, v3 = oacc[nt8][3] * i1;
        *(uint32_t*)(Ohi + grow0 + col)            = pack_hi(v0, v1);
        *(uint32_t*)(Olo + grow0 + col)            = pack_lo(v0, v1);
        *(uint32_t*)(Ohi + grow0 + 8 * EMB + col)  = pack_hi(v2, v3);
        *(uint32_t*)(Olo + grow0 + 8 * EMB + col)  = pack_lo(v2, v3);
    }
}

// ---------------------------------------------------------------------------
// Launch
// ---------------------------------------------------------------------------
extern "C" void kernel_launch(void* const* d_in, const int* in_sizes, int n_in,
                              void* d_out, int out_size)
{
    const float* x      = (const float*)d_in[0];
    const float* w_attn = (const float*)d_in[1];
    const float* b_attn = (const float*)d_in[2];
    const float* w_proj = (const float*)d_in[3];
    const float* b_proj = (const float*)d_in[4];
    float* out = (float*)d_out;

    ush *xhi, *xlo, *wah, *wal, *wph, *wpl, *athi, *atlo;
    ush *qh, *ql, *kh, *kl, *vh, *vl;
    cudaGetSymbolAddress((void**)&xhi,  g_xhi);
    cudaGetSymbolAddress((void**)&xlo,  g_xlo);
    cudaGetSymbolAddress((void**)&wah,  g_wah);
    cudaGetSymbolAddress((void**)&wal,  g_wal);
    cudaGetSymbolAddress((void**)&wph,  g_wph);
    cudaGetSymbolAddress((void**)&wpl,  g_wpl);
    cudaGetSymbolAddress((void**)&athi, g_athi);
    cudaGetSymbolAddress((void**)&atlo, g_atlo);
    cudaGetSymbolAddress((void**)&qh,   g_qh);
    cudaGetSymbolAddress((void**)&ql,   g_ql);
    cudaGetSymbolAddress((void**)&kh,   g_kh);
    cudaGetSymbolAddress((void**)&kl,   g_kl);
    cudaGetSymbolAddress((void**)&vh,   g_vh);
    cudaGetSymbolAddress((void**)&vl,   g_vl);

    cudaFuncSetAttribute(gemm_mma_split,
                         cudaFuncAttributeMaxDynamicSharedMemorySize, GEMM_SMEM);
    cudaFuncSetAttribute(gemm_qkv_split,
                         cudaFuncAttributeMaxDynamicSharedMemorySize, GEMM_SMEM);
    cudaFuncSetAttribute(attn_mma,
                         cudaFuncAttributeMaxDynamicSharedMemorySize, ATT_SMEM);

    // 1) split inputs/weights
    {
        int n = MTOT * EMB;
        convert_split<<<(n + 255) / 256, 256>>>(x, xhi, xlo, n);
        convert_transpose<<<dim3((3 * EMB) / 32, EMB / 32), dim3(32, 8)>>>(w_attn, wah, wal, EMB, 3 * EMB);
        convert_transpose<<<dim3(EMB / 32, EMB / 32), dim3(32, 8)>>>(w_proj, wph, wpl, EMB, EMB);
    }

    // 2) QKV projection with fused per-head split epilogue
    {
        dim3 grid((3 * EMB) / 128, MTOT / 128);
        gemm_qkv_split<<<grid, 256, GEMM_SMEM>>>(xhi, xlo, wah, wal, b_attn);
    }

    // 3) attention (tensor-core flash, 2 CTAs/SM)
    {
        dim3 grid(S_LEN / 128, HEADS, BATCH);
        attn_mma<<<grid, 256, ATT_SMEM>>>(qh, ql, kh, kl, vh, vl, athi, atlo);
    }

    // 4) output projection
    {
        dim3 grid(EMB / 128, MTOT / 128);
        gemm_mma_split<<<grid, 256, GEMM_SMEM>>>(athi, atlo, wph, wpl, b_proj, out,
                                                 MTOT, EMB, EMB);
    }
}

// round 10
// speedup vs baseline: 1.0330x; 1.0330x over previous
#include <cuda_runtime.h>
#include <cuda_bf16.h>
#include <math.h>
#include <stdint.h>

#define BATCH   2
#define S_LEN   2048
#define EMB     1024
#define HEADS   16
#define HD      64
#define NEG_VAL 100000.0f
#define MTOT    (BATCH * S_LEN)      // 4096

typedef unsigned short ush;

// ---------------------------------------------------------------------------
// Scratch (device globals; no runtime allocation allowed).
// ---------------------------------------------------------------------------
__device__ __align__(256) ush g_xhi[(size_t)MTOT * EMB];
__device__ __align__(256) ush g_xlo[(size_t)MTOT * EMB];
__device__ __align__(256) ush g_wah[(size_t)(3 * EMB) * EMB];
__device__ __align__(256) ush g_wal[(size_t)(3 * EMB) * EMB];
__device__ __align__(256) ush g_wph[(size_t)EMB * EMB];
__device__ __align__(256) ush g_wpl[(size_t)EMB * EMB];
__device__ __align__(256) ush g_athi[(size_t)MTOT * EMB];
__device__ __align__(256) ush g_atlo[(size_t)MTOT * EMB];
// Per-head split Q/K/V: [b][h][s][d]
__device__ __align__(256) ush g_qh[(size_t)MTOT * EMB];
__device__ __align__(256) ush g_ql[(size_t)MTOT * EMB];
__device__ __align__(256) ush g_kh[(size_t)MTOT * EMB];
__device__ __align__(256) ush g_kl[(size_t)MTOT * EMB];
__device__ __align__(256) ush g_vh[(size_t)MTOT * EMB];
__device__ __align__(256) ush g_vl[(size_t)MTOT * EMB];

// ---------------------------------------------------------------------------
// Helpers
// ---------------------------------------------------------------------------
__device__ __forceinline__ uint32_t smem_to_u32(const void* p) {
    uint32_t a;
    asm("{ .reg .u64 t; cvta.to.shared.u64 t, %1; cvt.u32.u64 %0, t; }" : "=r"(a) : "l"(p));
    return a;
}

#define CP_ASYNC16(dst, src) \
    asm volatile("cp.async.cg.shared.global [%0], [%1], 16;" :: "r"(dst), "l"(src))
#define CP_COMMIT() asm volatile("cp.async.commit_group;")
#define CP_WAIT1()  asm volatile("cp.async.wait_group 1;")
#define CP_WAIT0()  asm volatile("cp.async.wait_group 0;")

#define LDMX4(r0, r1, r2, r3, addr) \
    asm volatile("ldmatrix.sync.aligned.m8n8.x4.shared.b16 {%0,%1,%2,%3}, [%4];" \
                 : "=r"(r0), "=r"(r1), "=r"(r2), "=r"(r3) : "r"(addr))
#define LDMX4T(r0, r1, r2, r3, addr) \
    asm volatile("ldmatrix.sync.aligned.m8n8.x4.trans.shared.b16 {%0,%1,%2,%3}, [%4];" \
                 : "=r"(r0), "=r"(r1), "=r"(r2), "=r"(r3) : "r"(addr))

__device__ __forceinline__ void mma_bf16(float* d, const uint32_t* a, const uint32_t* b)
{
    asm volatile(
        "mma.sync.aligned.m16n8k16.row.col.f32.bf16.bf16.f32 "
        "{%0,%1,%2,%3}, {%4,%5,%6,%7}, {%8,%9}, {%0,%1,%2,%3};"
        : "+f"(d[0]), "+f"(d[1]), "+f"(d[2]), "+f"(d[3])
        : "r"(a[0]), "r"(a[1]), "r"(a[2]), "r"(a[3]), "r"(b[0]), "r"(b[1]));
}

// hi split via mantissa truncation (exact residual), pack two hi-bf16
__device__ __forceinline__ uint32_t pack_hi(float e, float o) {
    uint32_t r;
    asm("prmt.b32 %0, %1, %2, 0x7632;" : "=r"(r)
        : "r"(__float_as_uint(e)), "r"(__float_as_uint(o)));
    return r;
}
__device__ __forceinline__ uint32_t pack_lo(float e, float o) {
    float le = e - __uint_as_float(__float_as_uint(e) & 0xFFFF0000u);
    float lo = o - __uint_as_float(__float_as_uint(o) & 0xFFFF0000u);
    uint32_t r;
    asm("cvt.rn.bf16x2.f32 %0, %1, %2;" : "=r"(r) : "f"(lo), "f"(le));
    return r;
}

// ---------------------------------------------------------------------------
// fp32 -> bf16 hi/lo split (GEMM operand prep)
// ---------------------------------------------------------------------------
__global__ void convert_split(const float* __restrict__ in,
                              ush* __restrict__ hi, ush* __restrict__ lo, int n)
{
    int i = blockIdx.x * blockDim.x + threadIdx.x;
    if (i < n) {
        float v = in[i];
        __nv_bfloat16 h = __float2bfloat16(v);
        __nv_bfloat16 l = __float2bfloat16(v - __bfloat162float(h));
        hi[i] = *(ush*)&h;
        lo[i] = *(ush*)&l;
    }
}

__global__ void convert_transpose(const float* __restrict__ W,
                                  ush* __restrict__ hi, ush* __restrict__ lo,
                                  int K, int N)
{
    __shared__ float t[32][33];
    int n0 = blockIdx.x * 32, k0 = blockIdx.y * 32;
    int tx = threadIdx.x, ty = threadIdx.y;
#pragma unroll
    for (int i = 0; i < 4; i++)
        t[ty + i * 8][tx] = W[(size_t)(k0 + ty + i * 8) * N + n0 + tx];
    __syncthreads();
#pragma unroll
    for (int i = 0; i < 4; i++) {
        float v = t[tx][ty + i * 8];
        __nv_bfloat16 h = __float2bfloat16(v);
        __nv_bfloat16 l = __float2bfloat16(v - __bfloat162float(h));
        size_t o = (size_t)(n0 + ty + i * 8) * K + k0 + tx;
        hi[o] = *(ush*)&h;
        lo[o] = *(ush*)&l;
    }
}

// ---------------------------------------------------------------------------
// GEMM mainloop constants (128x128 tile, BK=32, 2-stage cp.async)
// ---------------------------------------------------------------------------
#define TROW      80
#define TILE_B    (128 * TROW)
#define STAGE_B   (4 * TILE_B)
#define GEMM_SMEM (2 * STAGE_B)          // 81920 -> 2 CTAs/SM

// ---------------------------------------------------------------------------
// Generic split-bf16 GEMM with fp32+bias output (used for proj)
// ---------------------------------------------------------------------------
__global__ __launch_bounds__(256, 2) void gemm_mma_split(
    const ush* __restrict__ Ahi, const ush* __restrict__ Alo,
    const ush* __restrict__ Bhi, const ush* __restrict__ Blo,
    const float* __restrict__ bias, float* __restrict__ C,
    int M, int N, int K)
{
    extern __shared__ char smem[];
    const uint32_t sb0 = smem_to_u32(smem);
    const int tid = threadIdx.x;
    const int wid = tid >> 5;
    const int l   = tid & 31;
    const int bx = blockIdx.x;
    const int by = blockIdx.y;
    const int wm = wid >> 2;
    const int wn = wid & 3;

    int r0 = tid >> 2,         cc0 = tid & 3;
    int r1 = (tid + 256) >> 2, cc1 = tid & 3;
    uint32_t so0 = (uint32_t)r0 * TROW + cc0 * 16;
    uint32_t so1 = (uint32_t)r1 * TROW + cc1 * 16;
    size_t ga0 = (size_t)(by * 128 + r0) * K + cc0 * 8;
    size_t ga1 = (size_t)(by * 128 + r1) * K + cc1 * 8;
    size_t gb0 = (size_t)(bx * 128 + r0) * K + cc0 * 8;
    size_t gb1 = (size_t)(bx * 128 + r1) * K + cc1 * 8;

    const int NT = K / 32;

    auto issue = [&](int kt) {
        uint32_t sb = sb0 + (uint32_t)(kt & 1) * STAGE_B;
        size_t ko = (size_t)kt * 32;
        CP_ASYNC16(sb + 0 * TILE_B + so0, Ahi + ga0 + ko);
        CP_ASYNC16(sb + 0 * TILE_B + so1, Ahi + ga1 + ko);
        CP_ASYNC16(sb + 1 * TILE_B + so0, Alo + ga0 + ko);
        CP_ASYNC16(sb + 1 * TILE_B + so1, Alo + ga1 + ko);
        CP_ASYNC16(sb + 2 * TILE_B + so0, Bhi + gb0 + ko);
        CP_ASYNC16(sb + 2 * TILE_B + so1, Bhi + gb1 + ko);
        CP_ASYNC16(sb + 3 * TILE_B + so0, Blo + gb0 + ko);
        CP_ASYNC16(sb + 3 * TILE_B + so1, Blo + gb1 + ko);
        CP_COMMIT();
    };

    float acc[4][4][4];
#pragma unroll
    for (int mi = 0; mi < 4; mi++)
#pragma unroll
        for (int j = 0; j < 4; j++)
#pragma unroll
            for (int e = 0; e < 4; e++) acc[mi][j][e] = 0.0f;

    const uint32_t a_lane = (uint32_t)(wm * 64 + (l & 15)) * TROW + (l >> 4) * 16;
    const uint32_t b_lane = (uint32_t)(wn * 32 + (l & 7) + ((l >> 4) * 8)) * TROW
                          + ((l >> 3) & 1) * 16;

    issue(0);

    for (int kt = 0; kt < NT; kt++) {
        if (kt + 1 < NT) { issue(kt + 1); CP_WAIT1(); }
        else             { CP_WAIT0(); }
        __syncthreads();

        uint32_t sb = sb0 + (uint32_t)(kt & 1) * STAGE_B;

#pragma unroll
        for (int ks8 = 0; ks8 < 2; ks8++) {
            const uint32_t ko = ks8 * 32;
            uint32_t ah[4][4], al[4][4], bh[2][4], bl[2][4];
#pragma unroll
            for (int mi = 0; mi < 4; mi++) {
                uint32_t ad = sb + a_lane + mi * (16 * TROW) + ko;
                LDMX4(ah[mi][0], ah[mi][1], ah[mi][2], ah[mi][3], ad);
                LDMX4(al[mi][0], al[mi][1], al[mi][2], al[mi][3], ad + TILE_B);
            }
#pragma unroll
            for (int nb = 0; nb < 2; nb++) {
                uint32_t bd = sb + 2 * TILE_B + b_lane + nb * (16 * TROW) + ko;
                LDMX4(bh[nb][0], bh[nb][1], bh[nb][2], bh[nb][3], bd);
                LDMX4(bl[nb][0], bl[nb][1], bl[nb][2], bl[nb][3], bd + TILE_B);
            }
#pragma unroll
            for (int mi = 0; mi < 4; mi++)
#pragma unroll
                for (int j = 0; j < 4; j++)
                    mma_bf16(acc[mi][j], ah[mi], &bh[j >> 1][(j & 1) * 2]);
#pragma unroll
            for (int mi = 0; mi < 4; mi++)
#pragma unroll
                for (int j = 0; j < 4; j++)
                    mma_bf16(acc[mi][j], ah[mi], &bl[j >> 1][(j & 1) * 2]);
#pragma unroll
            for (int mi = 0; mi < 4; mi++)
#pragma unroll
                for (int j = 0; j < 4; j++)
                    mma_bf16(acc[mi][j], al[mi], &bh[j >> 1][(j & 1) * 2]);
        }
        __syncthreads();
    }

#pragma unroll
    for (int mi = 0; mi < 4; mi++) {
        int row = by * 128 + wm * 64 + mi * 16 + (l >> 2);
#pragma unroll
        for (int j = 0; j < 4; j++) {
            int col = bx * 128 + wn * 32 + j * 8 + (l & 3) * 2;
            float b0 = bias[col], b1 = bias[col + 1];
            float2 v0 = make_float2(acc[mi][j][0] + b0, acc[mi][j][1] + b1);
            float2 v1 = make_float2(acc[mi][j][2] + b0, acc[mi][j][3] + b1);
            *(float2*)(C + (size_t)row * N + col)       = v0;
            *(float2*)(C + (size_t)(row + 8) * N + col) = v1;
        }
    }
}

// ---------------------------------------------------------------------------
// QKV GEMM with fused per-head hi/lo split epilogue (validated R9).
// N=3072, K=1024. col -> head h = col/192, section q/k/v = (col%192)/64.
// Q pre-scaled by 1/8 (exact power of two). Output: g_{q,k,v}{h,l}[b][h][s][d].
// ---------------------------------------------------------------------------
__global__ __launch_bounds__(256, 2) void gemm_qkv_split(
    const ush* __restrict__ Ahi, const ush* __restrict__ Alo,
    const ush* __restrict__ Bhi, const ush* __restrict__ Blo,
    const float* __restrict__ bias)
{
    const int K = EMB;
    extern __shared__ char smem[];
    const uint32_t sb0 = smem_to_u32(smem);
    const int tid = threadIdx.x;
    const int wid = tid >> 5;
    const int l   = tid & 31;
    const int bx = blockIdx.x;
    const int by = blockIdx.y;
    const int wm = wid >> 2;
    const int wn = wid & 3;

    int r0 = tid >> 2,         cc0 = tid & 3;
    int r1 = (tid + 256) >> 2, cc1 = tid & 3;
    uint32_t so0 = (uint32_t)r0 * TROW + cc0 * 16;
    uint32_t so1 = (uint32_t)r1 * TROW + cc1 * 16;
    size_t ga0 = (size_t)(by * 128 + r0) * K + cc0 * 8;
    size_t ga1 = (size_t)(by * 128 + r1) * K + cc1 * 8;
    size_t gb0 = (size_t)(bx * 128 + r0) * K + cc0 * 8;
    size_t gb1 = (size_t)(bx * 128 + r1) * K + cc1 * 8;

    const int NT = K / 32;

    auto issue = [&](int kt) {
        uint32_t sb = sb0 + (uint32_t)(kt & 1) * STAGE_B;
        size_t ko = (size_t)kt * 32;
        CP_ASYNC16(sb + 0 * TILE_B + so0, Ahi + ga0 + ko);
        CP_ASYNC16(sb + 0 * TILE_B + so1, Ahi + ga1 + ko);
        CP_ASYNC16(sb + 1 * TILE_B + so0, Alo + ga0 + ko);
        CP_ASYNC16(sb + 1 * TILE_B + so1, Alo + ga1 + ko);
        CP_ASYNC16(sb + 2 * TILE_B + so0, Bhi + gb0 + ko);
        CP_ASYNC16(sb + 2 * TILE_B + so1, Bhi + gb1 + ko);
        CP_ASYNC16(sb + 3 * TILE_B + so0, Blo + gb0 + ko);
        CP_ASYNC16(sb + 3 * TILE_B + so1, Blo + gb1 + ko);
        CP_COMMIT();
    };

    float acc[4][4][4];
#pragma unroll
    for (int mi = 0; mi < 4; mi++)
#pragma unroll
        for (int j = 0; j < 4; j++)
#pragma unroll
            for (int e = 0; e < 4; e++) acc[mi][j][e] = 0.0f;

    const uint32_t a_lane = (uint32_t)(wm * 64 + (l & 15)) * TROW + (l >> 4) * 16;
    const uint32_t b_lane = (uint32_t)(wn * 32 + (l & 7) + ((l >> 4) * 8)) * TROW
                          + ((l >> 3) & 1) * 16;

    issue(0);

    for (int kt = 0; kt < NT; kt++) {
        if (kt + 1 < NT) { issue(kt + 1); CP_WAIT1(); }
        else             { CP_WAIT0(); }
        __syncthreads();

        uint32_t sb = sb0 + (uint32_t)(kt & 1) * STAGE_B;

#pragma unroll
        for (int ks8 = 0; ks8 < 2; ks8++) {
            const uint32_t ko = ks8 * 32;
            uint32_t ah[4][4], al[4][4], bh[2][4], bl[2][4];
#pragma unroll
            for (int mi = 0; mi < 4; mi++) {
                uint32_t ad = sb + a_lane + mi * (16 * TROW) + ko;
                LDMX4(ah[mi][0], ah[mi][1], ah[mi][2], ah[mi][3], ad);
                LDMX4(al[mi][0], al[mi][1], al[mi][2], al[mi][3], ad + TILE_B);
            }
#pragma unroll
            for (int nb = 0; nb < 2; nb++) {
                uint32_t bd = sb + 2 * TILE_B + b_lane + nb * (16 * TROW) + ko;
                LDMX4(bh[nb][0], bh[nb][1], bh[nb][2], bh[nb][3], bd);
                LDMX4(bl[nb][0], bl[nb][1], bl[nb][2], bl[nb][3], bd + TILE_B);
            }
#pragma unroll
            for (int mi = 0; mi < 4; mi++)
#pragma unroll
                for (int j = 0; j < 4; j++)
                    mma_bf16(acc[mi][j], ah[mi], &bh[j >> 1][(j & 1) * 2]);
#pragma unroll
            for (int mi = 0; mi < 4; mi++)
#pragma unroll
                for (int j = 0; j < 4; j++)
                    mma_bf16(acc[mi][j], ah[mi], &bl[j >> 1][(j & 1) * 2]);
#pragma unroll
            for (int mi = 0; mi < 4; mi++)
#pragma unroll
                for (int j = 0; j < 4; j++)
                    mma_bf16(acc[mi][j], al[mi], &bh[j >> 1][(j & 1) * 2]);
        }
        __syncthreads();
    }

    // Fused epilogue: bias, route to per-head q/k/v, scale q by 1/8, split hi/lo.
#pragma unroll
    for (int mi = 0; mi < 4; mi++) {
        int row = by * 128 + wm * 64 + mi * 16 + (l >> 2);
        int b_ = row >> 11;          // / S_LEN
        int s  = row & (S_LEN - 1);
#pragma unroll
        for (int j = 0; j < 4; j++) {
            int col = bx * 128 + wn * 32 + j * 8 + (l & 3) * 2;
            float bb0 = bias[col], bb1 = bias[col + 1];
            float v0 = acc[mi][j][0] + bb0, v1 = acc[mi][j][1] + bb1;
            float v2 = acc[mi][j][2] + bb0, v3 = acc[mi][j][3] + bb1;

            int h  = col / 192;
            int w_ = col - h * 192;
            uint32_t *dh, *dl;
            int d;
            if (w_ < 64)       { dh = (uint32_t*)g_qh; dl = (uint32_t*)g_ql; d = w_;
                                 v0 *= 0.125f; v1 *= 0.125f; v2 *= 0.125f; v3 *= 0.125f; }
            else if (w_ < 128) { dh = (uint32_t*)g_kh; dl = (uint32_t*)g_kl; d = w_ - 64; }
            else               { dh = (uint32_t*)g_vh; dl = (uint32_t*)g_vl; d = w_ - 128; }

            size_t hb = ((size_t)(b_ * HEADS + h)) * S_LEN;
            size_t i0 = ((hb + s) * HD + d) >> 1;
            size_t i1 = ((hb + s + 8) * HD + d) >> 1;
            dh[i0] = pack_hi(v0, v1);  dl[i0] = pack_lo(v0, v1);
            dh[i1] = pack_hi(v2, v3);  dl[i1] = pack_lo(v2, v3);
        }
    }
}

// ---------------------------------------------------------------------------
// Flash attention, split-bf16 mma.sync (validated R6/R7: 128-row KV tiles).
// ---------------------------------------------------------------------------
#define AROW    144
#define ATILE   (128 * AROW)             // 18432
#define AQ_H    0
#define AQ_L    ATILE
#define ASTG    (2 * ATILE)              // stage base
#define ASTG_SZ (4 * ATILE)              // Kh,Kl,Vh,Vl per stage
#define ATT_SMEM (2 * ATILE + 2 * ASTG_SZ)   // 184320

__global__ __launch_bounds__(256) void attn_mma(
    const ush* __restrict__ Qh, const ush* __restrict__ Ql,
    const ush* __restrict__ Kh, const ush* __restrict__ Kl,
    const ush* __restrict__ Vh, const ush* __restrict__ Vl,
    ush* __restrict__ Ohi, ush* __restrict__ Olo)
{
    extern __shared__ char smem[];
    const uint32_t sb = smem_to_u32(smem);
    const int tid = threadIdx.x;
    const int w = tid >> 5;
    const int l = tid & 31;
    const int qt = (int)gridDim.x - 1 - (int)blockIdx.x;    // big tiles first
    const int h = blockIdx.y;
    const int b = blockIdx.z;
    const int qbase = qt * 128;

    const size_t headoff = (size_t)(b * HEADS + h) * S_LEN * HD;

    // 128x64 bf16 tile = 1024 16B-chunks; 4 per thread (8 chunks per row)
    auto issue_kv = [&](int kt) {
        uint32_t st = sb + ASTG + (uint32_t)(kt & 1) * ASTG_SZ;
        size_t gb = headoff + (size_t)kt * 128 * HD;
#pragma unroll
        for (int j = 0; j < 4; j++) {
            int c = tid + j * 256;
            int r = c >> 3;
            uint32_t dso = (uint32_t)r * AROW + (c & 7) * 16;
            size_t gso = gb + (size_t)r * HD + (c & 7) * 8;
            CP_ASYNC16(st + 0 * ATILE + dso, Kh + gso);
            CP_ASYNC16(st + 1 * ATILE + dso, Kl + gso);
            CP_ASYNC16(st + 2 * ATILE + dso, Vh + gso);
            CP_ASYNC16(st + 3 * ATILE + dso, Vl + gso);
        }
        CP_COMMIT();
    };

    // prologue group 0: Q tiles + KV stage 0
    {
        size_t gb = headoff + (size_t)qbase * HD;
        uint32_t st = sb + ASTG;
#pragma unroll
        for (int j = 0; j < 4; j++) {
            int c = tid + j * 256;
            int r = c >> 3;
            uint32_t dso = (uint32_t)r * AROW + (c & 7) * 16;
            size_t gso = gb + (size_t)r * HD + (c & 7) * 8;
            size_t kso = headoff + (size_t)r * HD + (c & 7) * 8;
            CP_ASYNC16(sb + AQ_H + dso, Qh + gso);
            CP_ASYNC16(sb + AQ_L + dso, Ql + gso);
            CP_ASYNC16(st + 0 * ATILE + dso, Kh + kso);
            CP_ASYNC16(st + 1 * ATILE + dso, Kl + kso);
            CP_ASYNC16(st + 2 * ATILE + dso, Vh + kso);
            CP_ASYNC16(st + 3 * ATILE + dso, Vl + kso);
        }
        CP_COMMIT();
    }

    // fragment lane addressing
    const uint32_t aq_lane = (uint32_t)(w * 16 + (l & 15)) * AROW + (l >> 4) * 16;
    const uint32_t kb_lane = (uint32_t)((l & 7) + ((l >> 4) * 8)) * AROW + ((l >> 3) & 1) * 16;
    const uint32_t v_lane  = (uint32_t)((l & 7) + ((l >> 3) & 1) * 8) * AROW + ((l >> 4) & 1) * 16;

    float oacc[8][4];
#pragma unroll
    for (int i = 0; i < 8; i++)
#pragma unroll
        for (int e = 0; e < 4; e++) oacc[i][e] = 0.0f;
    float rm0 = -INFINITY, rm1 = -INFINITY, rl0 = 0.0f, rl1 = 0.0f;

    const int row0 = qbase + w * 16 + (l >> 2);   // global q row for accum elems 0,1

    for (int kt = 0; kt <= qt; kt++) {
        if (kt < qt) { issue_kv(kt + 1); CP_WAIT1(); }
        else         { CP_WAIT0(); }
        __syncthreads();

        const uint32_t st = sb + ASTG + (uint32_t)(kt & 1) * ASTG_SZ;

        // ---- scores: S = Q @ K^T (3 passes) ----
        float sacc[16][4];
#pragma unroll
        for (int nt = 0; nt < 16; nt++)
#pragma unroll
            for (int e = 0; e < 4; e++) sacc[nt][e] = 0.0f;

#pragma unroll
        for (int ks = 0; ks < 4; ks++) {
            const uint32_t ko = ks * 32;
            uint32_t qhf[4], qlf[4];
            LDMX4(qhf[0], qhf[1], qhf[2], qhf[3], sb + AQ_H + aq_lane + ko);
            LDMX4(qlf[0], qlf[1], qlf[2], qlf[3], sb + AQ_L + aq_lane + ko);
#pragma unroll
            for (int nt2 = 0; nt2 < 8; nt2++) {
                uint32_t khf[4], klf[4];
                uint32_t kd = st + kb_lane + nt2 * (16 * AROW) + ko;
                LDMX4(khf[0], khf[1], khf[2], khf[3], kd);
                LDMX4(klf[0], klf[1], klf[2], klf[3], kd + ATILE);
                mma_bf16(sacc[2 * nt2],     qhf, &khf[0]);
                mma_bf16(sacc[2 * nt2 + 1], qhf, &khf[2]);
                mma_bf16(sacc[2 * nt2],     qhf, &klf[0]);
                mma_bf16(sacc[2 * nt2 + 1], qhf, &klf[2]);
                mma_bf16(sacc[2 * nt2],     qlf, &khf[0]);
                mma_bf16(sacc[2 * nt2 + 1], qlf, &khf[2]);
            }
        }

        // ---- causal mask (diagonal tile only) ----
        if (kt == qt) {
            const int cb = kt * 128 + (l & 3) * 2;
#pragma unroll
            for (int nt = 0; nt < 16; nt++) {
                int c = cb + nt * 8;
                if (c     > row0)     sacc[nt][0] = -NEG_VAL;
                if (c + 1 > row0)     sacc[nt][1] = -NEG_VAL;
                if (c     > row0 + 8) sacc[nt][2] = -NEG_VAL;
                if (c + 1 > row0 + 8) sacc[nt][3] = -NEG_VAL;
            }
        }

        // ---- online softmax (warp-local; rows live in quads) ----
        float mx0 = -INFINITY, mx1 = -INFINITY;
#pragma unroll
        for (int nt = 0; nt < 16; nt++) {
            mx0 = fmaxf(mx0, fmaxf(sacc[nt][0], sacc[nt][1]));
            mx1 = fmaxf(mx1, fmaxf(sacc[nt][2], sacc[nt][3]));
        }
        mx0 = fmaxf(mx0, __shfl_xor_sync(0xffffffffu, mx0, 1));
        mx0 = fmaxf(mx0, __shfl_xor_sync(0xffffffffu, mx0, 2));
        mx1 = fmaxf(mx1, __shfl_xor_sync(0xffffffffu, mx1, 1));
        mx1 = fmaxf(mx1, __shfl_xor_sync(0xffffffffu, mx1, 2));
        const float mn0 = fmaxf(rm0, mx0), mn1 = fmaxf(rm1, mx1);
        const float f0 = __expf(rm0 - mn0), f1 = __expf(rm1 - mn1);

        float s0 = 0.0f, s1 = 0.0f;
#pragma unroll
        for (int nt = 0; nt < 16; nt++) {
            float p0 = __expf(sacc[nt][0] - mn0);
            float p1 = __expf(sacc[nt][1] - mn0);
            float p2 = __expf(sacc[nt][2] - mn1);
            float p3 = __expf(sacc[nt][3] - mn1);
            sacc[nt][0] = p0; sacc[nt][1] = p1; sacc[nt][2] = p2; sacc[nt][3] = p3;
            s0 += p0 + p1; s1 += p2 + p3;
        }
        s0 += __shfl_xor_sync(0xffffffffu, s0, 1);
        s0 += __shfl_xor_sync(0xffffffffu, s0, 2);
        s1 += __shfl_xor_sync(0xffffffffu, s1, 1);
        s1 += __shfl_xor_sync(0xffffffffu, s1, 2);
        rl0 = rl0 * f0 + s0; rl1 = rl1 * f1 + s1;
        rm0 = mn0; rm1 = mn1;

#pragma unroll
        for (int i = 0; i < 8; i++) {
            oacc[i][0] *= f0; oacc[i][1] *= f0;
            oacc[i][2] *= f1; oacc[i][3] *= f1;
        }

        // ---- O += P @ V (3 passes, P converted in-register) ----
#pragma unroll
        for (int ks2 = 0; ks2 < 8; ks2++) {
            uint32_t aph[4], apl[4];
            float* p0 = sacc[2 * ks2];
            float* p1 = sacc[2 * ks2 + 1];
            aph[0] = pack_hi(p0[0], p0[1]);  apl[0] = pack_lo(p0[0], p0[1]);
            aph[1] = pack_hi(p0[2], p0[3]);  apl[1] = pack_lo(p0[2], p0[3]);
            aph[2] = pack_hi(p1[0], p1[1]);  apl[2] = pack_lo(p1[0], p1[1]);
            aph[3] = pack_hi(p1[2], p1[3]);  apl[3] = pack_lo(p1[2], p1[3]);

            const uint32_t kro = ks2 * (16 * AROW);
#pragma unroll
            for (int dv = 0; dv < 4; dv++) {
                uint32_t vhf[4], vlf[4];
                uint32_t va = st + 2 * ATILE + v_lane + kro + dv * 32;
                LDMX4T(vhf[0], vhf[1], vhf[2], vhf[3], va);
                LDMX4T(vlf[0], vlf[1], vlf[2], vlf[3], va + ATILE);
                mma_bf16(oacc[dv * 2],     aph, &vhf[0]);
                mma_bf16(oacc[dv * 2 + 1], aph, &vhf[2]);
                mma_bf16(oacc[dv * 2],     aph, &vlf[0]);
                mma_bf16(oacc[dv * 2 + 1], aph, &vlf[2]);
                mma_bf16(oacc[dv * 2],     apl, &vhf[0]);
                mma_bf16(oacc[dv * 2 + 1], apl, &vhf[2]);
            }
        }
        __syncthreads();
    }

    // ---- normalize, split, store merged-head layout ----
    const float i0 = 1.0f / rl0, i1 = 1.0f / rl1;
    const size_t grow0 = (size_t)(b * S_LEN + row0) * EMB;
#pragma unroll
    for (int nt8 = 0; nt8 < 8; nt8++) {
        int col = h * HD + nt8 * 8 + (l & 3) * 2;
        float v0 = oacc[nt8][0] * i0, v1 = oacc[nt8][1] * i0;
        float v2 = oacc[nt8][2] * i1, v3 = oacc[nt8][3] * i1;
        *(uint32_t*)(Ohi + grow0 + col)            = pack_hi(v0, v1);
        *(uint32_t*)(Olo + grow0 + col)            = pack_lo(v0, v1);
        *(uint32_t*)(Ohi + grow0 + 8 * EMB + col)  = pack_hi(v2, v3);
        *(uint32_t*)(Olo + grow0 + 8 * EMB + col)  = pack_lo(v2, v3);
    }
}

// ---------------------------------------------------------------------------
// Launch
// ---------------------------------------------------------------------------
extern "C" void kernel_launch(void* const* d_in, const int* in_sizes, int n_in,
                              void* d_out, int out_size)
{
    const float* x      = (const float*)d_in[0];
    const float* w_attn = (const float*)d_in[1];
    const float* b_attn = (const float*)d_in[2];
    const float* w_proj = (const float*)d_in[3];
    const float* b_proj = (const float*)d_in[4];
    float* out = (float*)d_out;

    ush *xhi, *xlo, *wah, *wal, *wph, *wpl, *athi, *atlo;
    ush *qh, *ql, *kh, *kl, *vh, *vl;
    cudaGetSymbolAddress((void**)&xhi,  g_xhi);
    cudaGetSymbolAddress((void**)&xlo,  g_xlo);
    cudaGetSymbolAddress((void**)&wah,  g_wah);
    cudaGetSymbolAddress((void**)&wal,  g_wal);
    cudaGetSymbolAddress((void**)&wph,  g_wph);
    cudaGetSymbolAddress((void**)&wpl,  g_wpl);
    cudaGetSymbolAddress((void**)&athi, g_athi);
    cudaGetSymbolAddress((void**)&atlo, g_atlo);
    cudaGetSymbolAddress((void**)&qh,   g_qh);
    cudaGetSymbolAddress((void**)&ql,   g_ql);
    cudaGetSymbolAddress((void**)&kh,   g_kh);
    cudaGetSymbolAddress((void**)&kl,   g_kl);
    cudaGetSymbolAddress((void**)&vh,   g_vh);
    cudaGetSymbolAddress((void**)&vl,   g_vl);

    cudaFuncSetAttribute(gemm_mma_split,
                         cudaFuncAttributeMaxDynamicSharedMemorySize, GEMM_SMEM);
    cudaFuncSetAttribute(gemm_qkv_split,
                         cudaFuncAttributeMaxDynamicSharedMemorySize, GEMM_SMEM);
    cudaFuncSetAttribute(attn_mma,
                         cudaFuncAttributeMaxDynamicSharedMemorySize, ATT_SMEM);

    // 1) split inputs/weights
    {
        int n = MTOT * EMB;
        convert_split<<<(n + 255) / 256, 256>>>(x, xhi, xlo, n);
        convert_transpose<<<dim3((3 * EMB) / 32, EMB / 32), dim3(32, 8)>>>(w_attn, wah, wal, EMB, 3 * EMB);
        convert_transpose<<<dim3(EMB / 32, EMB / 32), dim3(32, 8)>>>(w_proj, wph, wpl, EMB, EMB);
    }

    // 2) QKV projection with fused per-head split epilogue
    {
        dim3 grid((3 * EMB) / 128, MTOT / 128);
        gemm_qkv_split<<<grid, 256, GEMM_SMEM>>>(xhi, xlo, wah, wal, b_attn);
    }

    // 3) attention (tensor-core flash, 128-row KV tiles)
    {
        dim3 grid(S_LEN / 128, HEADS, BATCH);
        attn_mma<<<grid, 256, ATT_SMEM>>>(qh, ql, kh, kl, vh, vl, athi, atlo);
    }

    // 4) output projection
    {
        dim3 grid(EMB / 128, MTOT / 128);
        gemm_mma_split<<<grid, 256, GEMM_SMEM>>>(athi, atlo, wph, wpl, b_proj, out,
                                                 MTOT, EMB, EMB);
    }
}

// round 12
// speedup vs baseline: 1.3645x; 1.3209x over previous
#include <cuda_runtime.h>
#include <cuda_fp16.h>
#include <math.h>
#include <stdint.h>

#define BATCH   2
#define S_LEN   2048
#define EMB     1024
#define HEADS   16
#define HD      64
#define NEG_VAL 100000.0f
#define MTOT    (BATCH * S_LEN)      // 4096

typedef unsigned short ush;

// ---------------------------------------------------------------------------
// Scratch (device globals; no runtime allocation allowed).
// fp16 operands: A-side needs hi only (2-pass scheme), B-side needs hi+lo.
// ---------------------------------------------------------------------------
__device__ __align__(256) ush g_xhi[(size_t)MTOT * EMB];          // x fp16 [M][K]
__device__ __align__(256) ush g_wah[(size_t)(3 * EMB) * EMB];     // w_attn^T hi [N][K]
__device__ __align__(256) ush g_wal[(size_t)(3 * EMB) * EMB];     // w_attn^T lo
__device__ __align__(256) ush g_wph[(size_t)EMB * EMB];
__device__ __align__(256) ush g_wpl[(size_t)EMB * EMB];
__device__ __align__(256) ush g_athi[(size_t)MTOT * EMB];         // attn out fp16 [M][E]
// Per-head Q (hi only), K/V (hi+lo): [b][h][s][d]
__device__ __align__(256) ush g_qh[(size_t)MTOT * EMB];
__device__ __align__(256) ush g_kh[(size_t)MTOT * EMB];
__device__ __align__(256) ush g_kl[(size_t)MTOT * EMB];
__device__ __align__(256) ush g_vh[(size_t)MTOT * EMB];
__device__ __align__(256) ush g_vl[(size_t)MTOT * EMB];

// ---------------------------------------------------------------------------
// Helpers
// ---------------------------------------------------------------------------
__device__ __forceinline__ uint32_t smem_to_u32(const void* p) {
    uint32_t a;
    asm("{ .reg .u64 t; cvta.to.shared.u64 t, %1; cvt.u32.u64 %0, t; }" : "=r"(a) : "l"(p));
    return a;
}

#define CP_ASYNC16(dst, src) \
    asm volatile("cp.async.cg.shared.global [%0], [%1], 16;" :: "r"(dst), "l"(src))
#define CP_COMMIT() asm volatile("cp.async.commit_group;")
#define CP_WAIT1()  asm volatile("cp.async.wait_group 1;")
#define CP_WAIT0()  asm volatile("cp.async.wait_group 0;")

#define LDMX4(r0, r1, r2, r3, addr) \
    asm volatile("ldmatrix.sync.aligned.m8n8.x4.shared.b16 {%0,%1,%2,%3}, [%4];" \
                 : "=r"(r0), "=r"(r1), "=r"(r2), "=r"(r3) : "r"(addr))
#define LDMX4T(r0, r1, r2, r3, addr) \
    asm volatile("ldmatrix.sync.aligned.m8n8.x4.trans.shared.b16 {%0,%1,%2,%3}, [%4];" \
                 : "=r"(r0), "=r"(r1), "=r"(r2), "=r"(r3) : "r"(addr))

__device__ __forceinline__ void mma_f16(float* d, const uint32_t* a, const uint32_t* b)
{
    asm volatile(
        "mma.sync.aligned.m16n8k16.row.col.f32.f16.f16.f32 "
        "{%0,%1,%2,%3}, {%4,%5,%6,%7}, {%8,%9}, {%0,%1,%2,%3};"
        : "+f"(d[0]), "+f"(d[1]), "+f"(d[2]), "+f"(d[3])
        : "r"(a[0]), "r"(a[1]), "r"(a[2]), "r"(a[3]), "r"(b[0]), "r"(b[1]));
}

// pack two floats to fp16x2 (even in low half)
__device__ __forceinline__ uint32_t pack16(float e, float o) {
    uint32_t r;
    asm("cvt.rn.f16x2.f32 %0, %1, %2;" : "=r"(r) : "f"(o), "f"(e));
    return r;
}
// fp16 hi/lo split of a pair
__device__ __forceinline__ void split16(float e, float o, uint32_t& hi, uint32_t& lo) {
    __half he = __float2half_rn(e), ho = __float2half_rn(o);
    asm("mov.b32 %0, {%1, %2};" : "=r"(hi)
        : "h"(__half_as_ushort(he)), "h"(__half_as_ushort(ho)));
    float le = e - __half2float(he), lo_ = o - __half2float(ho);
    asm("cvt.rn.f16x2.f32 %0, %1, %2;" : "=r"(lo) : "f"(lo_), "f"(le));
}

// ---------------------------------------------------------------------------
// Conversions
// ---------------------------------------------------------------------------
__global__ void convert_x(const float* __restrict__ in, ush* __restrict__ hi, int n)
{
    int i = blockIdx.x * blockDim.x + threadIdx.x;
    if (i < n) {
        __half h = __float2half_rn(in[i]);
        hi[i] = __half_as_ushort(h);
    }
}

// W[K][N] fp32 row-major -> fp16 hi/lo [N][K] (transposed, K-major)
__global__ void convert_transpose(const float* __restrict__ W,
                                  ush* __restrict__ hi, ush* __restrict__ lo,
                                  int K, int N)
{
    __shared__ float t[32][33];
    int n0 = blockIdx.x * 32, k0 = blockIdx.y * 32;
    int tx = threadIdx.x, ty = threadIdx.y;
#pragma unroll
    for (int i = 0; i < 4; i++)
        t[ty + i * 8][tx] = W[(size_t)(k0 + ty + i * 8) * N + n0 + tx];
    __syncthreads();
#pragma unroll
    for (int i = 0; i < 4; i++) {
        float v = t[tx][ty + i * 8];
        __half h = __float2half_rn(v);
        float l = v - __half2float(h);
        size_t o = (size_t)(n0 + ty + i * 8) * K + k0 + tx;
        hi[o] = __half_as_ushort(h);
        lo[o] = __half_as_ushort(__float2half_rn(l));
    }
}

// ---------------------------------------------------------------------------
// GEMM mainloop constants (128x128 tile, BK=32, 2-stage cp.async, 3 tiles:
// Ahi, Bhi, Blo). 2-pass fp16: C ~= Ah*Bh + Ah*Bl.
// ---------------------------------------------------------------------------
#define TROW      80
#define TILE_B    (128 * TROW)
#define STAGE_B   (3 * TILE_B)
#define GEMM_SMEM (2 * STAGE_B)          // 61440 -> 2 CTAs/SM

// ---------------------------------------------------------------------------
// Generic fp16 2-pass GEMM, fp32+bias output (proj)
// ---------------------------------------------------------------------------
__global__ __launch_bounds__(256, 2) void gemm_mma_split(
    const ush* __restrict__ Ahi,
    const ush* __restrict__ Bhi, const ush* __restrict__ Blo,
    const float* __restrict__ bias, float* __restrict__ C,
    int M, int N, int K)
{
    extern __shared__ char smem[];
    const uint32_t sb0 = smem_to_u32(smem);
    const int tid = threadIdx.x;
    const int l   = tid & 31;
    const int wid = tid >> 5;
    const int bx = blockIdx.x;
    const int by = blockIdx.y;
    const int wm = wid >> 2;
    const int wn = wid & 3;

    int r0 = tid >> 2,         cc0 = tid & 3;
    int r1 = (tid + 256) >> 2, cc1 = tid & 3;
    uint32_t so0 = (uint32_t)r0 * TROW + cc0 * 16;
    uint32_t so1 = (uint32_t)r1 * TROW + cc1 * 16;
    size_t ga0 = (size_t)(by * 128 + r0) * K + cc0 * 8;
    size_t ga1 = (size_t)(by * 128 + r1) * K + cc1 * 8;
    size_t gb0 = (size_t)(bx * 128 + r0) * K + cc0 * 8;
    size_t gb1 = (size_t)(bx * 128 + r1) * K + cc1 * 8;

    const int NT = K / 32;

    auto issue = [&](int kt) {
        uint32_t sb = sb0 + (uint32_t)(kt & 1) * STAGE_B;
        size_t ko = (size_t)kt * 32;
        CP_ASYNC16(sb + 0 * TILE_B + so0, Ahi + ga0 + ko);
        CP_ASYNC16(sb + 0 * TILE_B + so1, Ahi + ga1 + ko);
        CP_ASYNC16(sb + 1 * TILE_B + so0, Bhi + gb0 + ko);
        CP_ASYNC16(sb + 1 * TILE_B + so1, Bhi + gb1 + ko);
        CP_ASYNC16(sb + 2 * TILE_B + so0, Blo + gb0 + ko);
        CP_ASYNC16(sb + 2 * TILE_B + so1, Blo + gb1 + ko);
        CP_COMMIT();
    };

    float acc[4][4][4];
#pragma unroll
    for (int mi = 0; mi < 4; mi++)
#pragma unroll
        for (int j = 0; j < 4; j++)
#pragma unroll
            for (int e = 0; e < 4; e++) acc[mi][j][e] = 0.0f;

    const uint32_t a_lane = (uint32_t)(wm * 64 + (l & 15)) * TROW + (l >> 4) * 16;
    const uint32_t b_lane = (uint32_t)(wn * 32 + (l & 7) + ((l >> 4) * 8)) * TROW
                          + ((l >> 3) & 1) * 16;

    issue(0);

    for (int kt = 0; kt < NT; kt++) {
        if (kt + 1 < NT) { issue(kt + 1); CP_WAIT1(); }
        else             { CP_WAIT0(); }
        __syncthreads();

        uint32_t sb = sb0 + (uint32_t)(kt & 1) * STAGE_B;

#pragma unroll
        for (int ks8 = 0; ks8 < 2; ks8++) {
            const uint32_t ko = ks8 * 32;
            uint32_t ah[4][4], bh[2][4], bl[2][4];
#pragma unroll
            for (int mi = 0; mi < 4; mi++) {
                uint32_t ad = sb + a_lane + mi * (16 * TROW) + ko;
                LDMX4(ah[mi][0], ah[mi][1], ah[mi][2], ah[mi][3], ad);
            }
#pragma unroll
            for (int nb = 0; nb < 2; nb++) {
                uint32_t bd = sb + 1 * TILE_B + b_lane + nb * (16 * TROW) + ko;
                LDMX4(bh[nb][0], bh[nb][1], bh[nb][2], bh[nb][3], bd);
                LDMX4(bl[nb][0], bl[nb][1], bl[nb][2], bl[nb][3], bd + TILE_B);
            }
#pragma unroll
            for (int mi = 0; mi < 4; mi++)
#pragma unroll
                for (int j = 0; j < 4; j++)
                    mma_f16(acc[mi][j], ah[mi], &bh[j >> 1][(j & 1) * 2]);
#pragma unroll
            for (int mi = 0; mi < 4; mi++)
#pragma unroll
                for (int j = 0; j < 4; j++)
                    mma_f16(acc[mi][j], ah[mi], &bl[j >> 1][(j & 1) * 2]);
        }
        __syncthreads();
    }

#pragma unroll
    for (int mi = 0; mi < 4; mi++) {
        int row = by * 128 + wm * 64 + mi * 16 + (l >> 2);
#pragma unroll
        for (int j = 0; j < 4; j++) {
            int col = bx * 128 + wn * 32 + j * 8 + (l & 3) * 2;
            float b0 = bias[col], b1 = bias[col + 1];
            float2 v0 = make_float2(acc[mi][j][0] + b0, acc[mi][j][1] + b1);
            float2 v1 = make_float2(acc[mi][j][2] + b0, acc[mi][j][3] + b1);
            *(float2*)(C + (size_t)row * N + col)       = v0;
            *(float2*)(C + (size_t)(row + 8) * N + col) = v1;
        }
    }
}

// ---------------------------------------------------------------------------
// QKV GEMM with fused per-head fp16 split epilogue.
// Q: hi only (pre-scaled 1/8); K/V: hi+lo.
// ---------------------------------------------------------------------------
__global__ __launch_bounds__(256, 2) void gemm_qkv_split(
    const ush* __restrict__ Ahi,
    const ush* __restrict__ Bhi, const ush* __restrict__ Blo,
    const float* __restrict__ bias)
{
    const int K = EMB;
    extern __shared__ char smem[];
    const uint32_t sb0 = smem_to_u32(smem);
    const int tid = threadIdx.x;
    const int l   = tid & 31;
    const int wid = tid >> 5;
    const int bx = blockIdx.x;
    const int by = blockIdx.y;
    const int wm = wid >> 2;
    const int wn = wid & 3;

    int r0 = tid >> 2,         cc0 = tid & 3;
    int r1 = (tid + 256) >> 2, cc1 = tid & 3;
    uint32_t so0 = (uint32_t)r0 * TROW + cc0 * 16;
    uint32_t so1 = (uint32_t)r1 * TROW + cc1 * 16;
    size_t ga0 = (size_t)(by * 128 + r0) * K + cc0 * 8;
    size_t ga1 = (size_t)(by * 128 + r1) * K + cc1 * 8;
    size_t gb0 = (size_t)(bx * 128 + r0) * K + cc0 * 8;
    size_t gb1 = (size_t)(bx * 128 + r1) * K + cc1 * 8;

    const int NT = K / 32;

    auto issue = [&](int kt) {
        uint32_t sb = sb0 + (uint32_t)(kt & 1) * STAGE_B;
        size_t ko = (size_t)kt * 32;
        CP_ASYNC16(sb + 0 * TILE_B + so0, Ahi + ga0 + ko);
        CP_ASYNC16(sb + 0 * TILE_B + so1, Ahi + ga1 + ko);
        CP_ASYNC16(sb + 1 * TILE_B + so0, Bhi + gb0 + ko);
        CP_ASYNC16(sb + 1 * TILE_B + so1, Bhi + gb1 + ko);
        CP_ASYNC16(sb + 2 * TILE_B + so0, Blo + gb0 + ko);
        CP_ASYNC16(sb + 2 * TILE_B + so1, Blo + gb1 + ko);
        CP_COMMIT();
    };

    float acc[4][4][4];
#pragma unroll
    for (int mi = 0; mi < 4; mi++)
#pragma unroll
        for (int j = 0; j < 4; j++)
#pragma unroll
            for (int e = 0; e < 4; e++) acc[mi][j][e] = 0.0f;

    const uint32_t a_lane = (uint32_t)(wm * 64 + (l & 15)) * TROW + (l >> 4) * 16;
    const uint32_t b_lane = (uint32_t)(wn * 32 + (l & 7) + ((l >> 4) * 8)) * TROW
                          + ((l >> 3) & 1) * 16;

    issue(0);

    for (int kt = 0; kt < NT; kt++) {
        if (kt + 1 < NT) { issue(kt + 1); CP_WAIT1(); }
        else             { CP_WAIT0(); }
        __syncthreads();

        uint32_t sb = sb0 + (uint32_t)(kt & 1) * STAGE_B;

#pragma unroll
        for (int ks8 = 0; ks8 < 2; ks8++) {
            const uint32_t ko = ks8 * 32;
            uint32_t ah[4][4], bh[2][4], bl[2][4];
#pragma unroll
            for (int mi = 0; mi < 4; mi++) {
                uint32_t ad = sb + a_lane + mi * (16 * TROW) + ko;
                LDMX4(ah[mi][0], ah[mi][1], ah[mi][2], ah[mi][3], ad);
            }
#pragma unroll
            for (int nb = 0; nb < 2; nb++) {
                uint32_t bd = sb + 1 * TILE_B + b_lane + nb * (16 * TROW) + ko;
                LDMX4(bh[nb][0], bh[nb][1], bh[nb][2], bh[nb][3], bd);
                LDMX4(bl[nb][0], bl[nb][1], bl[nb][2], bl[nb][3], bd + TILE_B);
            }
#pragma unroll
            for (int mi = 0; mi < 4; mi++)
#pragma unroll
                for (int j = 0; j < 4; j++)
                    mma_f16(acc[mi][j], ah[mi], &bh[j >> 1][(j & 1) * 2]);
#pragma unroll
            for (int mi = 0; mi < 4; mi++)
#pragma unroll
                for (int j = 0; j < 4; j++)
                    mma_f16(acc[mi][j], ah[mi], &bl[j >> 1][(j & 1) * 2]);
        }
        __syncthreads();
    }

    // Fused epilogue: bias; Q (scaled 1/8, hi only), K/V (hi+lo split).
#pragma unroll
    for (int mi = 0; mi < 4; mi++) {
        int row = by * 128 + wm * 64 + mi * 16 + (l >> 2);
        int b_ = row >> 11;
        int s  = row & (S_LEN - 1);
#pragma unroll
        for (int j = 0; j < 4; j++) {
            int col = bx * 128 + wn * 32 + j * 8 + (l & 3) * 2;
            float bb0 = bias[col], bb1 = bias[col + 1];
            float v0 = acc[mi][j][0] + bb0, v1 = acc[mi][j][1] + bb1;
            float v2 = acc[mi][j][2] + bb0, v3 = acc[mi][j][3] + bb1;

            int h  = col / 192;
            int w_ = col - h * 192;
            size_t hb = ((size_t)(b_ * HEADS + h)) * S_LEN;

            if (w_ < 64) {
                int d = w_;
                size_t i0 = ((hb + s) * HD + d) >> 1;
                size_t i1 = ((hb + s + 8) * HD + d) >> 1;
                ((uint32_t*)g_qh)[i0] = pack16(v0 * 0.125f, v1 * 0.125f);
                ((uint32_t*)g_qh)[i1] = pack16(v2 * 0.125f, v3 * 0.125f);
            } else if (w_ < 128) {
                int d = w_ - 64;
                size_t i0 = ((hb + s) * HD + d) >> 1;
                size_t i1 = ((hb + s + 8) * HD + d) >> 1;
                uint32_t hi, lo;
                split16(v0, v1, hi, lo);
                ((uint32_t*)g_kh)[i0] = hi; ((uint32_t*)g_kl)[i0] = lo;
                split16(v2, v3, hi, lo);
                ((uint32_t*)g_kh)[i1] = hi; ((uint32_t*)g_kl)[i1] = lo;
            } else {
                int d = w_ - 128;
                size_t i0 = ((hb + s) * HD + d) >> 1;
                size_t i1 = ((hb + s + 8) * HD + d) >> 1;
                uint32_t hi, lo;
                split16(v0, v1, hi, lo);
                ((uint32_t*)g_vh)[i0] = hi; ((uint32_t*)g_vl)[i0] = lo;
                split16(v2, v3, hi, lo);
                ((uint32_t*)g_vh)[i1] = hi; ((uint32_t*)g_vl)[i1] = lo;
            }
        }
    }
}

// ---------------------------------------------------------------------------
// Flash attention, fp16 2-pass mma.sync. 128-row KV tiles.
// Smem: Qh (1 tile) + 2 stages x {Kh,Kl,Vh,Vl}. Output: fp16 hi only.
// ---------------------------------------------------------------------------
#define AROW    144
#define ATILE   (128 * AROW)             // 18432
#define ASTG    ATILE                    // stage base (after Qh)
#define ASTG_SZ (4 * ATILE)
#define ATT_SMEM (ATILE + 2 * ASTG_SZ)   // 165888

__global__ __launch_bounds__(256) void attn_mma(
    const ush* __restrict__ Qh,
    const ush* __restrict__ Kh, const ush* __restrict__ Kl,
    const ush* __restrict__ Vh, const ush* __restrict__ Vl,
    ush* __restrict__ Ohi)
{
    extern __shared__ char smem[];
    const uint32_t sb = smem_to_u32(smem);
    const int tid = threadIdx.x;
    const int w = tid >> 5;
    const int l = tid & 31;
    const int qt = (int)gridDim.x - 1 - (int)blockIdx.x;    // big tiles first
    const int h = blockIdx.y;
    const int b = blockIdx.z;
    const int qbase = qt * 128;

    const size_t headoff = (size_t)(b * HEADS + h) * S_LEN * HD;

    auto issue_kv = [&](int kt) {
        uint32_t st = sb + ASTG + (uint32_t)(kt & 1) * ASTG_SZ;
        size_t gb = headoff + (size_t)kt * 128 * HD;
#pragma unroll
        for (int j = 0; j < 4; j++) {
            int c = tid + j * 256;
            int r = c >> 3;
            uint32_t dso = (uint32_t)r * AROW + (c & 7) * 16;
            size_t gso = gb + (size_t)r * HD + (c & 7) * 8;
            CP_ASYNC16(st + 0 * ATILE + dso, Kh + gso);
            CP_ASYNC16(st + 1 * ATILE + dso, Kl + gso);
            CP_ASYNC16(st + 2 * ATILE + dso, Vh + gso);
            CP_ASYNC16(st + 3 * ATILE + dso, Vl + gso);
        }
        CP_COMMIT();
    };

    // prologue: Qh + KV stage 0
    {
        size_t gb = headoff + (size_t)qbase * HD;
        uint32_t st = sb + ASTG;
#pragma unroll
        for (int j = 0; j < 4; j++) {
            int c = tid + j * 256;
            int r = c >> 3;
            uint32_t dso = (uint32_t)r * AROW + (c & 7) * 16;
            size_t gso = gb + (size_t)r * HD + (c & 7) * 8;
            size_t kso = headoff + (size_t)r * HD + (c & 7) * 8;
            CP_ASYNC16(sb + dso, Qh + gso);
            CP_ASYNC16(st + 0 * ATILE + dso, Kh + kso);
            CP_ASYNC16(st + 1 * ATILE + dso, Kl + kso);
            CP_ASYNC16(st + 2 * ATILE + dso, Vh + kso);
            CP_ASYNC16(st + 3 * ATILE + dso, Vl + kso);
        }
        CP_COMMIT();
    }

    const uint32_t aq_lane = (uint32_t)(w * 16 + (l & 15)) * AROW + (l >> 4) * 16;
    const uint32_t kb_lane = (uint32_t)((l & 7) + ((l >> 4) * 8)) * AROW + ((l >> 3) & 1) * 16;
    const uint32_t v_lane  = (uint32_t)((l & 7) + ((l >> 3) & 1) * 8) * AROW + ((l >> 4) & 1) * 16;

    float oacc[8][4];
#pragma unroll
    for (int i = 0; i < 8; i++)
#pragma unroll
        for (int e = 0; e < 4; e++) oacc[i][e] = 0.0f;
    float rm0 = -INFINITY, rm1 = -INFINITY, rl0 = 0.0f, rl1 = 0.0f;

    const int row0 = qbase + w * 16 + (l >> 2);

    for (int kt = 0; kt <= qt; kt++) {
        if (kt < qt) { issue_kv(kt + 1); CP_WAIT1(); }
        else         { CP_WAIT0(); }
        __syncthreads();

        const uint32_t st = sb + ASTG + (uint32_t)(kt & 1) * ASTG_SZ;

        // ---- scores: S = Qh @ (Kh + Kl)^T (2 passes) ----
        float sacc[16][4];
#pragma unroll
        for (int nt = 0; nt < 16; nt++)
#pragma unroll
            for (int e = 0; e < 4; e++) sacc[nt][e] = 0.0f;

#pragma unroll
        for (int ks = 0; ks < 4; ks++) {
            const uint32_t ko = ks * 32;
            uint32_t qhf[4];
            LDMX4(qhf[0], qhf[1], qhf[2], qhf[3], sb + aq_lane + ko);
#pragma unroll
            for (int nt2 = 0; nt2 < 8; nt2++) {
                uint32_t khf[4], klf[4];
                uint32_t kd = st + kb_lane + nt2 * (16 * AROW) + ko;
                LDMX4(khf[0], khf[1], khf[2], khf[3], kd);
                LDMX4(klf[0], klf[1], klf[2], klf[3], kd + ATILE);
                mma_f16(sacc[2 * nt2],     qhf, &khf[0]);
                mma_f16(sacc[2 * nt2 + 1], qhf, &khf[2]);
                mma_f16(sacc[2 * nt2],     qhf, &klf[0]);
                mma_f16(sacc[2 * nt2 + 1], qhf, &klf[2]);
            }
        }

        // ---- causal mask (diagonal tile only) ----
        if (kt == qt) {
            const int cb = kt * 128 + (l & 3) * 2;
#pragma unroll
            for (int nt = 0; nt < 16; nt++) {
                int c = cb + nt * 8;
                if (c     > row0)     sacc[nt][0] = -NEG_VAL;
                if (c + 1 > row0)     sacc[nt][1] = -NEG_VAL;
                if (c     > row0 + 8) sacc[nt][2] = -NEG_VAL;
                if (c + 1 > row0 + 8) sacc[nt][3] = -NEG_VAL;
            }
        }

        // ---- online softmax (warp-local; rows live in quads) ----
        float mx0 = -INFINITY, mx1 = -INFINITY;
#pragma unroll
        for (int nt = 0; nt < 16; nt++) {
            mx0 = fmaxf(mx0, fmaxf(sacc[nt][0], sacc[nt][1]));
            mx1 = fmaxf(mx1, fmaxf(sacc[nt][2], sacc[nt][3]));
        }
        mx0 = fmaxf(mx0, __shfl_xor_sync(0xffffffffu, mx0, 1));
        mx0 = fmaxf(mx0, __shfl_xor_sync(0xffffffffu, mx0, 2));
        mx1 = fmaxf(mx1, __shfl_xor_sync(0xffffffffu, mx1, 1));
        mx1 = fmaxf(mx1, __shfl_xor_sync(0xffffffffu, mx1, 2));
        const float mn0 = fmaxf(rm0, mx0), mn1 = fmaxf(rm1, mx1);
        const float f0 = __expf(rm0 - mn0), f1 = __expf(rm1 - mn1);

        float s0 = 0.0f, s1 = 0.0f;
#pragma unroll
        for (int nt = 0; nt < 16; nt++) {
            float p0 = __expf(sacc[nt][0] - mn0);
            float p1 = __expf(sacc[nt][1] - mn0);
            float p2 = __expf(sacc[nt][2] - mn1);
            float p3 = __expf(sacc[nt][3] - mn1);
            sacc[nt][0] = p0; sacc[nt][1] = p1; sacc[nt][2] = p2; sacc[nt][3] = p3;
            s0 += p0 + p1; s1 += p2 + p3;
        }
        s0 += __shfl_xor_sync(0xffffffffu, s0, 1);
        s0 += __shfl_xor_sync(0xffffffffu, s0, 2);
        s1 += __shfl_xor_sync(0xffffffffu, s1, 1);
        s1 += __shfl_xor_sync(0xffffffffu, s1, 2);
        rl0 = rl0 * f0 + s0; rl1 = rl1 * f1 + s1;
        rm0 = mn0; rm1 = mn1;

#pragma unroll
        for (int i = 0; i < 8; i++) {
            oacc[i][0] *= f0; oacc[i][1] *= f0;
            oacc[i][2] *= f1; oacc[i][3] *= f1;
        }

        // ---- O += Ph @ (Vh + Vl) (2 passes, P hi-converted in-register) ----
#pragma unroll
        for (int ks2 = 0; ks2 < 8; ks2++) {
            uint32_t aph[4];
            float* p0 = sacc[2 * ks2];
            float* p1 = sacc[2 * ks2 + 1];
            aph[0] = pack16(p0[0], p0[1]);
            aph[1] = pack16(p0[2], p0[3]);
            aph[2] = pack16(p1[0], p1[1]);
            aph[3] = pack16(p1[2], p1[3]);

            const uint32_t kro = ks2 * (16 * AROW);
#pragma unroll
            for (int dv = 0; dv < 4; dv++) {
                uint32_t vhf[4], vlf[4];
                uint32_t va = st + 2 * ATILE + v_lane + kro + dv * 32;
                LDMX4T(vhf[0], vhf[1], vhf[2], vhf[3], va);
                LDMX4T(vlf[0], vlf[1], vlf[2], vlf[3], va + ATILE);
                mma_f16(oacc[dv * 2],     aph, &vhf[0]);
                mma_f16(oacc[dv * 2 + 1], aph, &vhf[2]);
                mma_f16(oacc[dv * 2],     aph, &vlf[0]);
                mma_f16(oacc[dv * 2 + 1], aph, &vlf[2]);
            }
        }
        __syncthreads();
    }

    // ---- normalize, store fp16 merged-head layout ----
    const float i0 = 1.0f / rl0, i1 = 1.0f / rl1;
    const size_t grow0 = (size_t)(b * S_LEN + row0) * EMB;
#pragma unroll
    for (int nt8 = 0; nt8 < 8; nt8++) {
        int col = h * HD + nt8 * 8 + (l & 3) * 2;
        *(uint32_t*)(Ohi + grow0 + col) =
            pack16(oacc[nt8][0] * i0, oacc[nt8][1] * i0);
        *(uint32_t*)(Ohi + grow0 + 8 * EMB + col) =
            pack16(oacc[nt8][2] * i1, oacc[nt8][3] * i1);
    }
}

// ---------------------------------------------------------------------------
// Launch
// ---------------------------------------------------------------------------
extern "C" void kernel_launch(void* const* d_in, const int* in_sizes, int n_in,
                              void* d_out, int out_size)
{
    const float* x      = (const float*)d_in[0];
    const float* w_attn = (const float*)d_in[1];
    const float* b_attn = (const float*)d_in[2];
    const float* w_proj = (const float*)d_in[3];
    const float* b_proj = (const float*)d_in[4];
    float* out = (float*)d_out;

    ush *xhi, *wah, *wal, *wph, *wpl, *athi;
    ush *qh, *kh, *kl, *vh, *vl;
    cudaGetSymbolAddress((void**)&xhi,  g_xhi);
    cudaGetSymbolAddress((void**)&wah,  g_wah);
    cudaGetSymbolAddress((void**)&wal,  g_wal);
    cudaGetSymbolAddress((void**)&wph,  g_wph);
    cudaGetSymbolAddress((void**)&wpl,  g_wpl);
    cudaGetSymbolAddress((void**)&athi, g_athi);
    cudaGetSymbolAddress((void**)&qh,   g_qh);
    cudaGetSymbolAddress((void**)&kh,   g_kh);
    cudaGetSymbolAddress((void**)&kl,   g_kl);
    cudaGetSymbolAddress((void**)&vh,   g_vh);
    cudaGetSymbolAddress((void**)&vl,   g_vl);

    cudaFuncSetAttribute(gemm_mma_split,
                         cudaFuncAttributeMaxDynamicSharedMemorySize, GEMM_SMEM);
    cudaFuncSetAttribute(gemm_qkv_split,
                         cudaFuncAttributeMaxDynamicSharedMemorySize, GEMM_SMEM);
    cudaFuncSetAttribute(attn_mma,
                         cudaFuncAttributeMaxDynamicSharedMemorySize, ATT_SMEM);

    // 1) convert inputs/weights to fp16 (weights: transposed hi/lo split)
    {
        int n = MTOT * EMB;
        convert_x<<<(n + 255) / 256, 256>>>(x, xhi, n);
        convert_transpose<<<dim3((3 * EMB) / 32, EMB / 32), dim3(32, 8)>>>(w_attn, wah, wal, EMB, 3 * EMB);
        convert_transpose<<<dim3(EMB / 32, EMB / 32), dim3(32, 8)>>>(w_proj, wph, wpl, EMB, EMB);
    }

    // 2) QKV projection with fused per-head split epilogue
    {
        dim3 grid((3 * EMB) / 128, MTOT / 128);
        gemm_qkv_split<<<grid, 256, GEMM_SMEM>>>(xhi, wah, wal, b_attn);
    }

    // 3) attention (tensor-core flash, fp16 2-pass)
    {
        dim3 grid(S_LEN / 128, HEADS, BATCH);
        attn_mma<<<grid, 256, ATT_SMEM>>>(qh, kh, kl, vh, vl, athi);
    }

    // 4) output projection
    {
        dim3 grid(EMB / 128, MTOT / 128);
        gemm_mma_split<<<grid, 256, GEMM_SMEM>>>(athi, wph, wpl, b_proj, out,
                                                 MTOT, EMB, EMB);
    }
}

// round 13
// speedup vs baseline: 2.1304x; 1.5613x over previous
#include <cuda_runtime.h>
#include <cuda_fp16.h>
#include <math.h>
#include <stdint.h>

#define BATCH   2
#define S_LEN   2048
#define EMB     1024
#define HEADS   16
#define HD      64
#define NEG_VAL 100000.0f
#define MTOT    (BATCH * S_LEN)      // 4096

typedef unsigned short ush;

// ---------------------------------------------------------------------------
// Scratch (device globals; no runtime allocation allowed). Plain fp16.
// ---------------------------------------------------------------------------
__device__ __align__(256) ush g_xh[(size_t)MTOT * EMB];           // x fp16 [M][K]
__device__ __align__(256) ush g_wa[(size_t)(3 * EMB) * EMB];      // w_attn^T fp16 [N][K]
__device__ __align__(256) ush g_wp[(size_t)EMB * EMB];            // w_proj^T fp16 [N][K]
__device__ __align__(256) ush g_at[(size_t)MTOT * EMB];           // attn out fp16 [M][E]
// Per-head Q/K/V fp16: [b][h][s][d]
__device__ __align__(256) ush g_qh[(size_t)MTOT * EMB];
__device__ __align__(256) ush g_kh[(size_t)MTOT * EMB];
__device__ __align__(256) ush g_vh[(size_t)MTOT * EMB];

// ---------------------------------------------------------------------------
// Helpers
// ---------------------------------------------------------------------------
__device__ __forceinline__ uint32_t smem_to_u32(const void* p) {
    uint32_t a;
    asm("{ .reg .u64 t; cvta.to.shared.u64 t, %1; cvt.u32.u64 %0, t; }" : "=r"(a) : "l"(p));
    return a;
}

#define CP_ASYNC16(dst, src) \
    asm volatile("cp.async.cg.shared.global [%0], [%1], 16;" :: "r"(dst), "l"(src))
#define CP_COMMIT() asm volatile("cp.async.commit_group;")
#define CP_WAIT1()  asm volatile("cp.async.wait_group 1;")
#define CP_WAIT0()  asm volatile("cp.async.wait_group 0;")

#define LDMX4(r0, r1, r2, r3, addr) \
    asm volatile("ldmatrix.sync.aligned.m8n8.x4.shared.b16 {%0,%1,%2,%3}, [%4];" \
                 : "=r"(r0), "=r"(r1), "=r"(r2), "=r"(r3) : "r"(addr))
#define LDMX4T(r0, r1, r2, r3, addr) \
    asm volatile("ldmatrix.sync.aligned.m8n8.x4.trans.shared.b16 {%0,%1,%2,%3}, [%4];" \
                 : "=r"(r0), "=r"(r1), "=r"(r2), "=r"(r3) : "r"(addr))

__device__ __forceinline__ void mma_f16(float* d, const uint32_t* a, const uint32_t* b)
{
    asm volatile(
        "mma.sync.aligned.m16n8k16.row.col.f32.f16.f16.f32 "
        "{%0,%1,%2,%3}, {%4,%5,%6,%7}, {%8,%9}, {%0,%1,%2,%3};"
        : "+f"(d[0]), "+f"(d[1]), "+f"(d[2]), "+f"(d[3])
        : "r"(a[0]), "r"(a[1]), "r"(a[2]), "r"(a[3]), "r"(b[0]), "r"(b[1]));
}

// pack two floats to fp16x2 (even in low half)
__device__ __forceinline__ uint32_t pack16(float e, float o) {
    uint32_t r;
    asm("cvt.rn.f16x2.f32 %0, %1, %2;" : "=r"(r) : "f"(o), "f"(e));
    return r;
}

// ---------------------------------------------------------------------------
// Conversions
// ---------------------------------------------------------------------------
__global__ void convert_x(const float* __restrict__ in, ush* __restrict__ o16, int n)
{
    int i = blockIdx.x * blockDim.x + threadIdx.x;
    if (i < n) o16[i] = __half_as_ushort(__float2half_rn(in[i]));
}

// W[K][N] fp32 row-major -> fp16 [N][K] (transposed, K-major)
__global__ void convert_transpose(const float* __restrict__ W,
                                  ush* __restrict__ o16, int K, int N)
{
    __shared__ float t[32][33];
    int n0 = blockIdx.x * 32, k0 = blockIdx.y * 32;
    int tx = threadIdx.x, ty = threadIdx.y;
#pragma unroll
    for (int i = 0; i < 4; i++)
        t[ty + i * 8][tx] = W[(size_t)(k0 + ty + i * 8) * N + n0 + tx];
    __syncthreads();
#pragma unroll
    for (int i = 0; i < 4; i++) {
        float v = t[tx][ty + i * 8];
        size_t o = (size_t)(n0 + ty + i * 8) * K + k0 + tx;
        o16[o] = __half_as_ushort(__float2half_rn(v));
    }
}

// ---------------------------------------------------------------------------
// GEMM mainloop constants (128x128 tile, BK=32, 2-stage cp.async, 2 tiles)
// ---------------------------------------------------------------------------
#define TROW      80
#define TILE_B    (128 * TROW)
#define STAGE_B   (2 * TILE_B)
#define GEMM_SMEM (2 * STAGE_B)          // 40960 -> 2 CTAs/SM (reg-limited)

// ---------------------------------------------------------------------------
// Plain fp16 GEMM, fp32+bias output (proj)
// ---------------------------------------------------------------------------
__global__ __launch_bounds__(256, 2) void gemm_f16(
    const ush* __restrict__ A, const ush* __restrict__ B,
    const float* __restrict__ bias, float* __restrict__ C,
    int M, int N, int K)
{
    extern __shared__ char smem[];
    const uint32_t sb0 = smem_to_u32(smem);
    const int tid = threadIdx.x;
    const int l   = tid & 31;
    const int wid = tid >> 5;
    const int bx = blockIdx.x;
    const int by = blockIdx.y;
    const int wm = wid >> 2;
    const int wn = wid & 3;

    int r0 = tid >> 2,         cc0 = tid & 3;
    int r1 = (tid + 256) >> 2, cc1 = tid & 3;
    uint32_t so0 = (uint32_t)r0 * TROW + cc0 * 16;
    uint32_t so1 = (uint32_t)r1 * TROW + cc1 * 16;
    size_t ga0 = (size_t)(by * 128 + r0) * K + cc0 * 8;
    size_t ga1 = (size_t)(by * 128 + r1) * K + cc1 * 8;
    size_t gb0 = (size_t)(bx * 128 + r0) * K + cc0 * 8;
    size_t gb1 = (size_t)(bx * 128 + r1) * K + cc1 * 8;

    const int NT = K / 32;

    auto issue = [&](int kt) {
        uint32_t sb = sb0 + (uint32_t)(kt & 1) * STAGE_B;
        size_t ko = (size_t)kt * 32;
        CP_ASYNC16(sb + 0 * TILE_B + so0, A + ga0 + ko);
        CP_ASYNC16(sb + 0 * TILE_B + so1, A + ga1 + ko);
        CP_ASYNC16(sb + 1 * TILE_B + so0, B + gb0 + ko);
        CP_ASYNC16(sb + 1 * TILE_B + so1, B + gb1 + ko);
        CP_COMMIT();
    };

    float acc[4][4][4];
#pragma unroll
    for (int mi = 0; mi < 4; mi++)
#pragma unroll
        for (int j = 0; j < 4; j++)
#pragma unroll
            for (int e = 0; e < 4; e++) acc[mi][j][e] = 0.0f;

    const uint32_t a_lane = (uint32_t)(wm * 64 + (l & 15)) * TROW + (l >> 4) * 16;
    const uint32_t b_lane = (uint32_t)(wn * 32 + (l & 7) + ((l >> 4) * 8)) * TROW
                          + ((l >> 3) & 1) * 16;

    issue(0);

    for (int kt = 0; kt < NT; kt++) {
        if (kt + 1 < NT) { issue(kt + 1); CP_WAIT1(); }
        else             { CP_WAIT0(); }
        __syncthreads();

        uint32_t sb = sb0 + (uint32_t)(kt & 1) * STAGE_B;

#pragma unroll
        for (int ks8 = 0; ks8 < 2; ks8++) {
            const uint32_t ko = ks8 * 32;
            uint32_t ah[4][4], bh[2][4];
#pragma unroll
            for (int mi = 0; mi < 4; mi++) {
                uint32_t ad = sb + a_lane + mi * (16 * TROW) + ko;
                LDMX4(ah[mi][0], ah[mi][1], ah[mi][2], ah[mi][3], ad);
            }
#pragma unroll
            for (int nb = 0; nb < 2; nb++) {
                uint32_t bd = sb + 1 * TILE_B + b_lane + nb * (16 * TROW) + ko;
                LDMX4(bh[nb][0], bh[nb][1], bh[nb][2], bh[nb][3], bd);
            }
#pragma unroll
            for (int mi = 0; mi < 4; mi++)
#pragma unroll
                for (int j = 0; j < 4; j++)
                    mma_f16(acc[mi][j], ah[mi], &bh[j >> 1][(j & 1) * 2]);
        }
        __syncthreads();
    }

#pragma unroll
    for (int mi = 0; mi < 4; mi++) {
        int row = by * 128 + wm * 64 + mi * 16 + (l >> 2);
#pragma unroll
        for (int j = 0; j < 4; j++) {
            int col = bx * 128 + wn * 32 + j * 8 + (l & 3) * 2;
            float b0 = bias[col], b1 = bias[col + 1];
            float2 v0 = make_float2(acc[mi][j][0] + b0, acc[mi][j][1] + b1);
            float2 v1 = make_float2(acc[mi][j][2] + b0, acc[mi][j][3] + b1);
            *(float2*)(C + (size_t)row * N + col)       = v0;
            *(float2*)(C + (size_t)(row + 8) * N + col) = v1;
        }
    }
}

// ---------------------------------------------------------------------------
// QKV GEMM with fused per-head fp16 epilogue (Q pre-scaled by 1/8).
// ---------------------------------------------------------------------------
__global__ __launch_bounds__(256, 2) void gemm_qkv_split(
    const ush* __restrict__ A, const ush* __restrict__ B,
    const float* __restrict__ bias)
{
    const int K = EMB;
    extern __shared__ char smem[];
    const uint32_t sb0 = smem_to_u32(smem);
    const int tid = threadIdx.x;
    const int l   = tid & 31;
    const int wid = tid >> 5;
    const int bx = blockIdx.x;
    const int by = blockIdx.y;
    const int wm = wid >> 2;
    const int wn = wid & 3;

    int r0 = tid >> 2,         cc0 = tid & 3;
    int r1 = (tid + 256) >> 2, cc1 = tid & 3;
    uint32_t so0 = (uint32_t)r0 * TROW + cc0 * 16;
    uint32_t so1 = (uint32_t)r1 * TROW + cc1 * 16;
    size_t ga0 = (size_t)(by * 128 + r0) * K + cc0 * 8;
    size_t ga1 = (size_t)(by * 128 + r1) * K + cc1 * 8;
    size_t gb0 = (size_t)(bx * 128 + r0) * K + cc0 * 8;
    size_t gb1 = (size_t)(bx * 128 + r1) * K + cc1 * 8;

    const int NT = K / 32;

    auto issue = [&](int kt) {
        uint32_t sb = sb0 + (uint32_t)(kt & 1) * STAGE_B;
        size_t ko = (size_t)kt * 32;
        CP_ASYNC16(sb + 0 * TILE_B + so0, A + ga0 + ko);
        CP_ASYNC16(sb + 0 * TILE_B + so1, A + ga1 + ko);
        CP_ASYNC16(sb + 1 * TILE_B + so0, B + gb0 + ko);
        CP_ASYNC16(sb + 1 * TILE_B + so1, B + gb1 + ko);
        CP_COMMIT();
    };

    float acc[4][4][4];
#pragma unroll
    for (int mi = 0; mi < 4; mi++)
#pragma unroll
        for (int j = 0; j < 4; j++)
#pragma unroll
            for (int e = 0; e < 4; e++) acc[mi][j][e] = 0.0f;

    const uint32_t a_lane = (uint32_t)(wm * 64 + (l & 15)) * TROW + (l >> 4) * 16;
    const uint32_t b_lane = (uint32_t)(wn * 32 + (l & 7) + ((l >> 4) * 8)) * TROW
                          + ((l >> 3) & 1) * 16;

    issue(0);

    for (int kt = 0; kt < NT; kt++) {
        if (kt + 1 < NT) { issue(kt + 1); CP_WAIT1(); }
        else             { CP_WAIT0(); }
        __syncthreads();

        uint32_t sb = sb0 + (uint32_t)(kt & 1) * STAGE_B;

#pragma unroll
        for (int ks8 = 0; ks8 < 2; ks8++) {
            const uint32_t ko = ks8 * 32;
            uint32_t ah[4][4], bh[2][4];
#pragma unroll
            for (int mi = 0; mi < 4; mi++) {
                uint32_t ad = sb + a_lane + mi * (16 * TROW) + ko;
                LDMX4(ah[mi][0], ah[mi][1], ah[mi][2], ah[mi][3], ad);
            }
#pragma unroll
            for (int nb = 0; nb < 2; nb++) {
                uint32_t bd = sb + 1 * TILE_B + b_lane + nb * (16 * TROW) + ko;
                LDMX4(bh[nb][0], bh[nb][1], bh[nb][2], bh[nb][3], bd);
            }
#pragma unroll
            for (int mi = 0; mi < 4; mi++)
#pragma unroll
                for (int j = 0; j < 4; j++)
                    mma_f16(acc[mi][j], ah[mi], &bh[j >> 1][(j & 1) * 2]);
        }
        __syncthreads();
    }

    // Fused epilogue: bias; route to per-head q/k/v; scale q by 1/8.
#pragma unroll
    for (int mi = 0; mi < 4; mi++) {
        int row = by * 128 + wm * 64 + mi * 16 + (l >> 2);
        int b_ = row >> 11;
        int s  = row & (S_LEN - 1);
#pragma unroll
        for (int j = 0; j < 4; j++) {
            int col = bx * 128 + wn * 32 + j * 8 + (l & 3) * 2;
            float bb0 = bias[col], bb1 = bias[col + 1];
            float v0 = acc[mi][j][0] + bb0, v1 = acc[mi][j][1] + bb1;
            float v2 = acc[mi][j][2] + bb0, v3 = acc[mi][j][3] + bb1;

            int h  = col / 192;
            int w_ = col - h * 192;
            uint32_t* dst;
            int d;
            if (w_ < 64)       { dst = (uint32_t*)g_qh; d = w_;
                                 v0 *= 0.125f; v1 *= 0.125f; v2 *= 0.125f; v3 *= 0.125f; }
            else if (w_ < 128) { dst = (uint32_t*)g_kh; d = w_ - 64; }
            else               { dst = (uint32_t*)g_vh; d = w_ - 128; }

            size_t hb = ((size_t)(b_ * HEADS + h)) * S_LEN;
            dst[((hb + s) * HD + d) >> 1]     = pack16(v0, v1);
            dst[((hb + s + 8) * HD + d) >> 1] = pack16(v2, v3);
        }
    }
}

// ---------------------------------------------------------------------------
// Flash attention, plain fp16 mma.sync. 128-row KV tiles.
// Smem: Q + 2 stages x {K, V} = 92160 B -> 2 CTAs/SM.
// ---------------------------------------------------------------------------
#define AROW    144
#define ATILE   (128 * AROW)             // 18432
#define ASTG    ATILE                    // stage base (after Q)
#define ASTG_SZ (2 * ATILE)              // K, V
#define ATT_SMEM (ATILE + 2 * ASTG_SZ)   // 92160

__global__ __launch_bounds__(256, 2) void attn_mma(
    const ush* __restrict__ Qh,
    const ush* __restrict__ Kh, const ush* __restrict__ Vh,
    ush* __restrict__ O16)
{
    extern __shared__ char smem[];
    const uint32_t sb = smem_to_u32(smem);
    const int tid = threadIdx.x;
    const int w = tid >> 5;
    const int l = tid & 31;
    const int qt = (int)gridDim.x - 1 - (int)blockIdx.x;    // big tiles first
    const int h = blockIdx.y;
    const int b = blockIdx.z;
    const int qbase = qt * 128;

    const size_t headoff = (size_t)(b * HEADS + h) * S_LEN * HD;

    auto issue_kv = [&](int kt) {
        uint32_t st = sb + ASTG + (uint32_t)(kt & 1) * ASTG_SZ;
        size_t gb = headoff + (size_t)kt * 128 * HD;
#pragma unroll
        for (int j = 0; j < 4; j++) {
            int c = tid + j * 256;
            int r = c >> 3;
            uint32_t dso = (uint32_t)r * AROW + (c & 7) * 16;
            size_t gso = gb + (size_t)r * HD + (c & 7) * 8;
            CP_ASYNC16(st + 0 * ATILE + dso, Kh + gso);
            CP_ASYNC16(st + 1 * ATILE + dso, Vh + gso);
        }
        CP_COMMIT();
    };

    // prologue: Q + KV stage 0
    {
        size_t gb = headoff + (size_t)qbase * HD;
        uint32_t st = sb + ASTG;
#pragma unroll
        for (int j = 0; j < 4; j++) {
            int c = tid + j * 256;
            int r = c >> 3;
            uint32_t dso = (uint32_t)r * AROW + (c & 7) * 16;
            size_t gso = gb + (size_t)r * HD + (c & 7) * 8;
            size_t kso = headoff + (size_t)r * HD + (c & 7) * 8;
            CP_ASYNC16(sb + dso, Qh + gso);
            CP_ASYNC16(st + 0 * ATILE + dso, Kh + kso);
            CP_ASYNC16(st + 1 * ATILE + dso, Vh + kso);
        }
        CP_COMMIT();
    }

    const uint32_t aq_lane = (uint32_t)(w * 16 + (l & 15)) * AROW + (l >> 4) * 16;
    const uint32_t kb_lane = (uint32_t)((l & 7) + ((l >> 4) * 8)) * AROW + ((l >> 3) & 1) * 16;
    const uint32_t v_lane  = (uint32_t)((l & 7) + ((l >> 3) & 1) * 8) * AROW + ((l >> 4) & 1) * 16;

    float oacc[8][4];
#pragma unroll
    for (int i = 0; i < 8; i++)
#pragma unroll
        for (int e = 0; e < 4; e++) oacc[i][e] = 0.0f;
    float rm0 = -INFINITY, rm1 = -INFINITY, rl0 = 0.0f, rl1 = 0.0f;

    const int row0 = qbase + w * 16 + (l >> 2);

    for (int kt = 0; kt <= qt; kt++) {
        if (kt < qt) { issue_kv(kt + 1); CP_WAIT1(); }
        else         { CP_WAIT0(); }
        __syncthreads();

        const uint32_t st = sb + ASTG + (uint32_t)(kt & 1) * ASTG_SZ;

        // ---- scores: S = Q @ K^T ----
        float sacc[16][4];
#pragma unroll
        for (int nt = 0; nt < 16; nt++)
#pragma unroll
            for (int e = 0; e < 4; e++) sacc[nt][e] = 0.0f;

#pragma unroll
        for (int ks = 0; ks < 4; ks++) {
            const uint32_t ko = ks * 32;
            uint32_t qhf[4];
            LDMX4(qhf[0], qhf[1], qhf[2], qhf[3], sb + aq_lane + ko);
#pragma unroll
            for (int nt2 = 0; nt2 < 8; nt2++) {
                uint32_t khf[4];
                uint32_t kd = st + kb_lane + nt2 * (16 * AROW) + ko;
                LDMX4(khf[0], khf[1], khf[2], khf[3], kd);
                mma_f16(sacc[2 * nt2],     qhf, &khf[0]);
                mma_f16(sacc[2 * nt2 + 1], qhf, &khf[2]);
            }
        }

        // ---- causal mask (diagonal tile only) ----
        if (kt == qt) {
            const int cb = kt * 128 + (l & 3) * 2;
#pragma unroll
            for (int nt = 0; nt < 16; nt++) {
                int c = cb + nt * 8;
                if (c     > row0)     sacc[nt][0] = -NEG_VAL;
                if (c + 1 > row0)     sacc[nt][1] = -NEG_VAL;
                if (c     > row0 + 8) sacc[nt][2] = -NEG_VAL;
                if (c + 1 > row0 + 8) sacc[nt][3] = -NEG_VAL;
            }
        }

        // ---- online softmax (warp-local; rows live in quads) ----
        float mx0 = -INFINITY, mx1 = -INFINITY;
#pragma unroll
        for (int nt = 0; nt < 16; nt++) {
            mx0 = fmaxf(mx0, fmaxf(sacc[nt][0], sacc[nt][1]));
            mx1 = fmaxf(mx1, fmaxf(sacc[nt][2], sacc[nt][3]));
        }
        mx0 = fmaxf(mx0, __shfl_xor_sync(0xffffffffu, mx0, 1));
        mx0 = fmaxf(mx0, __shfl_xor_sync(0xffffffffu, mx0, 2));
        mx1 = fmaxf(mx1, __shfl_xor_sync(0xffffffffu, mx1, 1));
        mx1 = fmaxf(mx1, __shfl_xor_sync(0xffffffffu, mx1, 2));
        const float mn0 = fmaxf(rm0, mx0), mn1 = fmaxf(rm1, mx1);
        const float f0 = __expf(rm0 - mn0), f1 = __expf(rm1 - mn1);

        float s0 = 0.0f, s1 = 0.0f;
#pragma unroll
        for (int nt = 0; nt < 16; nt++) {
            float p0 = __expf(sacc[nt][0] - mn0);
            float p1 = __expf(sacc[nt][1] - mn0);
            float p2 = __expf(sacc[nt][2] - mn1);
            float p3 = __expf(sacc[nt][3] - mn1);
            sacc[nt][0] = p0; sacc[nt][1] = p1; sacc[nt][2] = p2; sacc[nt][3] = p3;
            s0 += p0 + p1; s1 += p2 + p3;
        }
        s0 += __shfl_xor_sync(0xffffffffu, s0, 1);
        s0 += __shfl_xor_sync(0xffffffffu, s0, 2);
        s1 += __shfl_xor_sync(0xffffffffu, s1, 1);
        s1 += __shfl_xor_sync(0xffffffffu, s1, 2);
        rl0 = rl0 * f0 + s0; rl1 = rl1 * f1 + s1;
        rm0 = mn0; rm1 = mn1;

#pragma unroll
        for (int i = 0; i < 8; i++) {
            oacc[i][0] *= f0; oacc[i][1] *= f0;
            oacc[i][2] *= f1; oacc[i][3] *= f1;
        }

        // ---- O += P @ V (P fp16-converted in-register) ----
#pragma unroll
        for (int ks2 = 0; ks2 < 8; ks2++) {
            uint32_t aph[4];
            float* p0 = sacc[2 * ks2];
            float* p1 = sacc[2 * ks2 + 1];
            aph[0] = pack16(p0[0], p0[1]);
            aph[1] = pack16(p0[2], p0[3]);
            aph[2] = pack16(p1[0], p1[1]);
            aph[3] = pack16(p1[2], p1[3]);

            const uint32_t kro = ks2 * (16 * AROW);
#pragma unroll
            for (int dv = 0; dv < 4; dv++) {
                uint32_t vhf[4];
                uint32_t va = st + 1 * ATILE + v_lane + kro + dv * 32;
                LDMX4T(vhf[0], vhf[1], vhf[2], vhf[3], va);
                mma_f16(oacc[dv * 2],     aph, &vhf[0]);
                mma_f16(oacc[dv * 2 + 1], aph, &vhf[2]);
            }
        }
        __syncthreads();
    }

    // ---- normalize, store fp16 merged-head layout ----
    const float i0 = 1.0f / rl0, i1 = 1.0f / rl1;
    const size_t grow0 = (size_t)(b * S_LEN + row0) * EMB;
#pragma unroll
    for (int nt8 = 0; nt8 < 8; nt8++) {
        int col = h * HD + nt8 * 8 + (l & 3) * 2;
        *(uint32_t*)(O16 + grow0 + col) =
            pack16(oacc[nt8][0] * i0, oacc[nt8][1] * i0);
        *(uint32_t*)(O16 + grow0 + 8 * EMB + col) =
            pack16(oacc[nt8][2] * i1, oacc[nt8][3] * i1);
    }
}

// ---------------------------------------------------------------------------
// Launch
// ---------------------------------------------------------------------------
extern "C" void kernel_launch(void* const* d_in, const int* in_sizes, int n_in,
                              void* d_out, int out_size)
{
    const float* x      = (const float*)d_in[0];
    const float* w_attn = (const float*)d_in[1];
    const float* b_attn = (const float*)d_in[2];
    const float* w_proj = (const float*)d_in[3];
    const float* b_proj = (const float*)d_in[4];
    float* out = (float*)d_out;

    ush *xh, *wa, *wp, *at, *qh, *kh, *vh;
    cudaGetSymbolAddress((void**)&xh, g_xh);
    cudaGetSymbolAddress((void**)&wa, g_wa);
    cudaGetSymbolAddress((void**)&wp, g_wp);
    cudaGetSymbolAddress((void**)&at, g_at);
    cudaGetSymbolAddress((void**)&qh, g_qh);
    cudaGetSymbolAddress((void**)&kh, g_kh);
    cudaGetSymbolAddress((void**)&vh, g_vh);

    cudaFuncSetAttribute(gemm_f16,
                         cudaFuncAttributeMaxDynamicSharedMemorySize, GEMM_SMEM);
    cudaFuncSetAttribute(gemm_qkv_split,
                         cudaFuncAttributeMaxDynamicSharedMemorySize, GEMM_SMEM);
    cudaFuncSetAttribute(attn_mma,
                         cudaFuncAttributeMaxDynamicSharedMemorySize, ATT_SMEM);

    // 1) convert inputs/weights to fp16 (weights transposed to [N][K])
    {
        int n = MTOT * EMB;
        convert_x<<<(n + 255) / 256, 256>>>(x, xh, n);
        convert_transpose<<<dim3((3 * EMB) / 32, EMB / 32), dim3(32, 8)>>>(w_attn, wa, EMB, 3 * EMB);
        convert_transpose<<<dim3(EMB / 32, EMB / 32), dim3(32, 8)>>>(w_proj, wp, EMB, EMB);
    }

    // 2) QKV projection with fused per-head epilogue
    {
        dim3 grid((3 * EMB) / 128, MTOT / 128);
        gemm_qkv_split<<<grid, 256, GEMM_SMEM>>>(xh, wa, b_attn);
    }

    // 3) attention (tensor-core flash, plain fp16, 2 CTAs/SM)
    {
        dim3 grid(S_LEN / 128, HEADS, BATCH);
        attn_mma<<<grid, 256, ATT_SMEM>>>(qh, kh, vh, at);
    }

    // 4) output projection
    {
        dim3 grid(EMB / 128, MTOT / 128);
        gemm_f16<<<grid, 256, GEMM_SMEM>>>(at, wp, b_proj, out, MTOT, EMB, EMB);
    }
}

// round 15
// speedup vs baseline: 2.3141x; 1.0862x over previous
#include <cuda_runtime.h>
#include <cuda_fp16.h>
#include <math.h>
#include <stdint.h>

#define BATCH   2
#define S_LEN   2048
#define EMB     1024
#define HEADS   16
#define HD      64
#define NEG_VAL 100000.0f
#define MTOT    (BATCH * S_LEN)      // 4096

typedef unsigned short ush;

// ---------------------------------------------------------------------------
// Scratch (device globals; no runtime allocation allowed). Plain fp16.
// ---------------------------------------------------------------------------
__device__ __align__(256) ush g_xh[(size_t)MTOT * EMB];           // x fp16 [M][K]
__device__ __align__(256) ush g_wa[(size_t)(3 * EMB) * EMB];      // w_attn^T fp16 [N][K]
__device__ __align__(256) ush g_wp[(size_t)EMB * EMB];            // w_proj^T fp16 [N][K]
__device__ __align__(256) ush g_at[(size_t)MTOT * EMB];           // attn out fp16 [M][E]
// Per-head Q/K/V fp16: [b][h][s][d]
__device__ __align__(256) ush g_qh[(size_t)MTOT * EMB];
__device__ __align__(256) ush g_kh[(size_t)MTOT * EMB];
__device__ __align__(256) ush g_vh[(size_t)MTOT * EMB];

// ---------------------------------------------------------------------------
// Helpers
// ---------------------------------------------------------------------------
__device__ __forceinline__ uint32_t smem_to_u32(const void* p) {
    uint32_t a;
    asm("{ .reg .u64 t; cvta.to.shared.u64 t, %1; cvt.u32.u64 %0, t; }" : "=r"(a) : "l"(p));
    return a;
}

#define CP_ASYNC16(dst, src) \
    asm volatile("cp.async.cg.shared.global [%0], [%1], 16;" :: "r"(dst), "l"(src))
#define CP_COMMIT() asm volatile("cp.async.commit_group;")
#define CP_WAIT1()  asm volatile("cp.async.wait_group 1;")
#define CP_WAIT0()  asm volatile("cp.async.wait_group 0;")

#define LDMX4(r0, r1, r2, r3, addr) \
    asm volatile("ldmatrix.sync.aligned.m8n8.x4.shared.b16 {%0,%1,%2,%3}, [%4];" \
                 : "=r"(r0), "=r"(r1), "=r"(r2), "=r"(r3) : "r"(addr))
#define LDMX4T(r0, r1, r2, r3, addr) \
    asm volatile("ldmatrix.sync.aligned.m8n8.x4.trans.shared.b16 {%0,%1,%2,%3}, [%4];" \
                 : "=r"(r0), "=r"(r1), "=r"(r2), "=r"(r3) : "r"(addr))

__device__ __forceinline__ void mma_f16(float* d, const uint32_t* a, const uint32_t* b)
{
    asm volatile(
        "mma.sync.aligned.m16n8k16.row.col.f32.f16.f16.f32 "
        "{%0,%1,%2,%3}, {%4,%5,%6,%7}, {%8,%9}, {%0,%1,%2,%3};"
        : "+f"(d[0]), "+f"(d[1]), "+f"(d[2]), "+f"(d[3])
        : "r"(a[0]), "r"(a[1]), "r"(a[2]), "r"(a[3]), "r"(b[0]), "r"(b[1]));
}

// pack two floats to fp16x2 (even in low half)
__device__ __forceinline__ uint32_t pack16(float e, float o) {
    uint32_t r;
    asm("cvt.rn.f16x2.f32 %0, %1, %2;" : "=r"(r) : "f"(o), "f"(e));
    return r;
}

// ---------------------------------------------------------------------------
// Conversions
// ---------------------------------------------------------------------------
__global__ void convert_x(const float* __restrict__ in, ush* __restrict__ o16, int n)
{
    int i = blockIdx.x * blockDim.x + threadIdx.x;
    if (i < n) o16[i] = __half_as_ushort(__float2half_rn(in[i]));
}

// W[K][N] fp32 row-major -> fp16 [N][K] (transposed, K-major)
__global__ void convert_transpose(const float* __restrict__ W,
                                  ush* __restrict__ o16, int K, int N)
{
    __shared__ float t[32][33];
    int n0 = blockIdx.x * 32, k0 = blockIdx.y * 32;
    int tx = threadIdx.x, ty = threadIdx.y;
#pragma unroll
    for (int i = 0; i < 4; i++)
        t[ty + i * 8][tx] = W[(size_t)(k0 + ty + i * 8) * N + n0 + tx];
    __syncthreads();
#pragma unroll
    for (int i = 0; i < 4; i++) {
        float v = t[tx][ty + i * 8];
        size_t o = (size_t)(n0 + ty + i * 8) * K + k0 + tx;
        o16[o] = __half_as_ushort(__float2half_rn(v));
    }
}

// ---------------------------------------------------------------------------
// GEMM mainloop constants: 128x128 tile, BK=64 per barrier, 2-stage cp.async.
// Tiles are 128 rows x 64 fp16 = 128 B data/row, stride 144 B (conflict-free).
// ---------------------------------------------------------------------------
#define GROW      144
#define GTILE     (128 * GROW)           // 18432
#define GSTAGE    (2 * GTILE)            // A + B
#define GEMM_SMEM (2 * GSTAGE)           // 73728 -> 2 CTAs/SM (reg-limited)

// ---------------------------------------------------------------------------
// Plain fp16 GEMM, fp32+bias output (proj)
// ---------------------------------------------------------------------------
__global__ __launch_bounds__(256, 2) void gemm_f16(
    const ush* __restrict__ A, const ush* __restrict__ B,
    const float* __restrict__ bias, float* __restrict__ C,
    int M, int N, int K)
{
    extern __shared__ char smem[];
    const uint32_t sb0 = smem_to_u32(smem);
    const int tid = threadIdx.x;
    const int l   = tid & 31;
    const int wid = tid >> 5;
    const int bx = blockIdx.x;
    const int by = blockIdx.y;
    const int wm = wid >> 2;
    const int wn = wid & 3;

    const int NT = K / 64;

    auto issue = [&](int kt) {
        uint32_t sb = sb0 + (uint32_t)(kt & 1) * GSTAGE;
        size_t ko = (size_t)kt * 64;
#pragma unroll
        for (int j = 0; j < 4; j++) {
            int c = tid + j * 256;
            int r = c >> 3, cc = c & 7;
            uint32_t dso = (uint32_t)r * GROW + cc * 16;
            CP_ASYNC16(sb + dso,         A + (size_t)(by * 128 + r) * K + ko + cc * 8);
            CP_ASYNC16(sb + GTILE + dso, B + (size_t)(bx * 128 + r) * K + ko + cc * 8);
        }
        CP_COMMIT();
    };

    float acc[4][4][4];
#pragma unroll
    for (int mi = 0; mi < 4; mi++)
#pragma unroll
        for (int j = 0; j < 4; j++)
#pragma unroll
            for (int e = 0; e < 4; e++) acc[mi][j][e] = 0.0f;

    const uint32_t a_lane = (uint32_t)(wm * 64 + (l & 15)) * GROW + (l >> 4) * 16;
    const uint32_t b_lane = (uint32_t)(wn * 32 + (l & 7) + ((l >> 4) * 8)) * GROW
                          + ((l >> 3) & 1) * 16;

    issue(0);

    for (int kt = 0; kt < NT; kt++) {
        if (kt + 1 < NT) { issue(kt + 1); CP_WAIT1(); }
        else             { CP_WAIT0(); }
        __syncthreads();

        uint32_t sb = sb0 + (uint32_t)(kt & 1) * GSTAGE;

#pragma unroll
        for (int ks = 0; ks < 4; ks++) {
            const uint32_t ko = ks * 32;
            uint32_t ah[4][4], bh[2][4];
#pragma unroll
            for (int mi = 0; mi < 4; mi++) {
                uint32_t ad = sb + a_lane + mi * (16 * GROW) + ko;
                LDMX4(ah[mi][0], ah[mi][1], ah[mi][2], ah[mi][3], ad);
            }
#pragma unroll
            for (int nb = 0; nb < 2; nb++) {
                uint32_t bd = sb + GTILE + b_lane + nb * (16 * GROW) + ko;
                LDMX4(bh[nb][0], bh[nb][1], bh[nb][2], bh[nb][3], bd);
            }
#pragma unroll
            for (int mi = 0; mi < 4; mi++)
#pragma unroll
                for (int j = 0; j < 4; j++)
                    mma_f16(acc[mi][j], ah[mi], &bh[j >> 1][(j & 1) * 2]);
        }
        __syncthreads();
    }

#pragma unroll
    for (int mi = 0; mi < 4; mi++) {
        int row = by * 128 + wm * 64 + mi * 16 + (l >> 2);
#pragma unroll
        for (int j = 0; j < 4; j++) {
            int col = bx * 128 + wn * 32 + j * 8 + (l & 3) * 2;
            float b0 = bias[col], b1 = bias[col + 1];
            float2 v0 = make_float2(acc[mi][j][0] + b0, acc[mi][j][1] + b1);
            float2 v1 = make_float2(acc[mi][j][2] + b0, acc[mi][j][3] + b1);
            *(float2*)(C + (size_t)row * N + col)       = v0;
            *(float2*)(C + (size_t)(row + 8) * N + col) = v1;
        }
    }
}

// ---------------------------------------------------------------------------
// QKV GEMM with fused per-head fp16 epilogue (Q pre-scaled by 1/8).
// ---------------------------------------------------------------------------
__global__ __launch_bounds__(256, 2) void gemm_qkv_split(
    const ush* __restrict__ A, const ush* __restrict__ B,
    const float* __restrict__ bias)
{
    const int K = EMB;
    extern __shared__ char smem[];
    const uint32_t sb0 = smem_to_u32(smem);
    const int tid = threadIdx.x;
    const int l   = tid & 31;
    const int wid = tid >> 5;
    const int bx = blockIdx.x;
    const int by = blockIdx.y;
    const int wm = wid >> 2;
    const int wn = wid & 3;

    const int NT = K / 64;

    auto issue = [&](int kt) {
        uint32_t sb = sb0 + (uint32_t)(kt & 1) * GSTAGE;
        size_t ko = (size_t)kt * 64;
#pragma unroll
        for (int j = 0; j < 4; j++) {
            int c = tid + j * 256;
            int r = c >> 3, cc = c & 7;
            uint32_t dso = (uint32_t)r * GROW + cc * 16;
            CP_ASYNC16(sb + dso,         A + (size_t)(by * 128 + r) * K + ko + cc * 8);
            CP_ASYNC16(sb + GTILE + dso, B + (size_t)(bx * 128 + r) * K + ko + cc * 8);
        }
        CP_COMMIT();
    };

    float acc[4][4][4];
#pragma unroll
    for (int mi = 0; mi < 4; mi++)
#pragma unroll
        for (int j = 0; j < 4; j++)
#pragma unroll
            for (int e = 0; e < 4; e++) acc[mi][j][e] = 0.0f;

    const uint32_t a_lane = (uint32_t)(wm * 64 + (l & 15)) * GROW + (l >> 4) * 16;
    const uint32_t b_lane = (uint32_t)(wn * 32 + (l & 7) + ((l >> 4) * 8)) * GROW
                          + ((l >> 3) & 1) * 16;

    issue(0);

    for (int kt = 0; kt < NT; kt++) {
        if (kt + 1 < NT) { issue(kt + 1); CP_WAIT1(); }
        else             { CP_WAIT0(); }
        __syncthreads();

        uint32_t sb = sb0 + (uint32_t)(kt & 1) * GSTAGE;

#pragma unroll
        for (int ks = 0; ks < 4; ks++) {
            const uint32_t ko = ks * 32;
            uint32_t ah[4][4], bh[2][4];
#pragma unroll
            for (int mi = 0; mi < 4; mi++) {
                uint32_t ad = sb + a_lane + mi * (16 * GROW) + ko;
                LDMX4(ah[mi][0], ah[mi][1], ah[mi][2], ah[mi][3], ad);
            }
#pragma unroll
            for (int nb = 0; nb < 2; nb++) {
                uint32_t bd = sb + GTILE + b_lane + nb * (16 * GROW) + ko;
                LDMX4(bh[nb][0], bh[nb][1], bh[nb][2], bh[nb][3], bd);
            }
#pragma unroll
            for (int mi = 0; mi < 4; mi++)
#pragma unroll
                for (int j = 0; j < 4; j++)
                    mma_f16(acc[mi][j], ah[mi], &bh[j >> 1][(j & 1) * 2]);
        }
        __syncthreads();
    }

    // Fused epilogue: bias; route to per-head q/k/v; scale q by 1/8.
#pragma unroll
    for (int mi = 0; mi < 4; mi++) {
        int row = by * 128 + wm * 64 + mi * 16 + (l >> 2);
        int b_ = row >> 11;
        int s  = row & (S_LEN - 1);
#pragma unroll
        for (int j = 0; j < 4; j++) {
            int col = bx * 128 + wn * 32 + j * 8 + (l & 3) * 2;
            float bb0 = bias[col], bb1 = bias[col + 1];
            float v0 = acc[mi][j][0] + bb0, v1 = acc[mi][j][1] + bb1;
            float v2 = acc[mi][j][2] + bb0, v3 = acc[mi][j][3] + bb1;

            int h  = col / 192;
            int w_ = col - h * 192;
            uint32_t* dst;
            int d;
            if (w_ < 64)       { dst = (uint32_t*)g_qh; d = w_;
                                 v0 *= 0.125f; v1 *= 0.125f; v2 *= 0.125f; v3 *= 0.125f; }
            else if (w_ < 128) { dst = (uint32_t*)g_kh; d = w_ - 64; }
            else               { dst = (uint32_t*)g_vh; d = w_ - 128; }

            size_t hb = ((size_t)(b_ * HEADS + h)) * S_LEN;
            dst[((hb + s) * HD + d) >> 1]     = pack16(v0, v1);
            dst[((hb + s + 8) * HD + d) >> 1] = pack16(v2, v3);
        }
    }
}

// ---------------------------------------------------------------------------
// Flash attention, plain fp16 mma.sync (validated R13). 128-row KV tiles.
// Smem: Q + 2 stages x {K, V} = 92160 B -> 2 CTAs/SM.
// ---------------------------------------------------------------------------
#define AROW    144
#define ATILE   (128 * AROW)             // 18432
#define ASTG    ATILE                    // stage base (after Q)
#define ASTG_SZ (2 * ATILE)              // K, V
#define ATT_SMEM (ATILE + 2 * ASTG_SZ)   // 92160

__global__ __launch_bounds__(256, 2) void attn_mma(
    const ush* __restrict__ Qh,
    const ush* __restrict__ Kh, const ush* __restrict__ Vh,
    ush* __restrict__ O16)
{
    extern __shared__ char smem[];
    const uint32_t sb = smem_to_u32(smem);
    const int tid = threadIdx.x;
    const int w = tid >> 5;
    const int l = tid & 31;
    const int qt = (int)gridDim.x - 1 - (int)blockIdx.x;    // big tiles first
    const int h = blockIdx.y;
    const int b = blockIdx.z;
    const int qbase = qt * 128;

    const size_t headoff = (size_t)(b * HEADS + h) * S_LEN * HD;

    auto issue_kv = [&](int kt) {
        uint32_t st = sb + ASTG + (uint32_t)(kt & 1) * ASTG_SZ;
        size_t gb = headoff + (size_t)kt * 128 * HD;
#pragma unroll
        for (int j = 0; j < 4; j++) {
            int c = tid + j * 256;
            int r = c >> 3;
            uint32_t dso = (uint32_t)r * AROW + (c & 7) * 16;
            size_t gso = gb + (size_t)r * HD + (c & 7) * 8;
            CP_ASYNC16(st + 0 * ATILE + dso, Kh + gso);
            CP_ASYNC16(st + 1 * ATILE + dso, Vh + gso);
        }
        CP_COMMIT();
    };

    // prologue: Q + KV stage 0
    {
        size_t gb = headoff + (size_t)qbase * HD;
        uint32_t st = sb + ASTG;
#pragma unroll
        for (int j = 0; j < 4; j++) {
            int c = tid + j * 256;
            int r = c >> 3;
            uint32_t dso = (uint32_t)r * AROW + (c & 7) * 16;
            size_t gso = gb + (size_t)r * HD + (c & 7) * 8;
            size_t kso = headoff + (size_t)r * HD + (c & 7) * 8;
            CP_ASYNC16(sb + dso, Qh + gso);
            CP_ASYNC16(st + 0 * ATILE + dso, Kh + kso);
            CP_ASYNC16(st + 1 * ATILE + dso, Vh + kso);
        }
        CP_COMMIT();
    }

    const uint32_t aq_lane = (uint32_t)(w * 16 + (l & 15)) * AROW + (l >> 4) * 16;
    const uint32_t kb_lane = (uint32_t)((l & 7) + ((l >> 4) * 8)) * AROW + ((l >> 3) & 1) * 16;
    const uint32_t v_lane  = (uint32_t)((l & 7) + ((l >> 3) & 1) * 8) * AROW + ((l >> 4) & 1) * 16;

    float oacc[8][4];
#pragma unroll
    for (int i = 0; i < 8; i++)
#pragma unroll
        for (int e = 0; e < 4; e++) oacc[i][e] = 0.0f;
    float rm0 = -INFINITY, rm1 = -INFINITY, rl0 = 0.0f, rl1 = 0.0f;

    const int row0 = qbase + w * 16 + (l >> 2);

    for (int kt = 0; kt <= qt; kt++) {
        if (kt < qt) { issue_kv(kt + 1); CP_WAIT1(); }
        else         { CP_WAIT0(); }
        __syncthreads();

        const uint32_t st = sb + ASTG + (uint32_t)(kt & 1) * ASTG_SZ;

        // ---- scores: S = Q @ K^T ----
        float sacc[16][4];
#pragma unroll
        for (int nt = 0; nt < 16; nt++)
#pragma unroll
            for (int e = 0; e < 4; e++) sacc[nt][e] = 0.0f;

#pragma unroll
        for (int ks = 0; ks < 4; ks++) {
            const uint32_t ko = ks * 32;
            uint32_t qhf[4];
            LDMX4(qhf[0], qhf[1], qhf[2], qhf[3], sb + aq_lane + ko);
#pragma unroll
            for (int nt2 = 0; nt2 < 8; nt2++) {
                uint32_t khf[4];
                uint32_t kd = st + kb_lane + nt2 * (16 * AROW) + ko;
                LDMX4(khf[0], khf[1], khf[2], khf[3], kd);
                mma_f16(sacc[2 * nt2],     qhf, &khf[0]);
                mma_f16(sacc[2 * nt2 + 1], qhf, &khf[2]);
            }
        }

        // ---- causal mask (diagonal tile only) ----
        if (kt == qt) {
            const int cb = kt * 128 + (l & 3) * 2;
#pragma unroll
            for (int nt = 0; nt < 16; nt++) {
                int c = cb + nt * 8;
                if (c     > row0)     sacc[nt][0] = -NEG_VAL;
                if (c + 1 > row0)     sacc[nt][1] = -NEG_VAL;
                if (c     > row0 + 8) sacc[nt][2] = -NEG_VAL;
                if (c + 1 > row0 + 8) sacc[nt][3] = -NEG_VAL;
            }
        }

        // ---- online softmax (warp-local; rows live in quads) ----
        float mx0 = -INFINITY, mx1 = -INFINITY;
#pragma unroll
        for (int nt = 0; nt < 16; nt++) {
            mx0 = fmaxf(mx0, fmaxf(sacc[nt][0], sacc[nt][1]));
            mx1 = fmaxf(mx1, fmaxf(sacc[nt][2], sacc[nt][3]));
        }
        mx0 = fmaxf(mx0, __shfl_xor_sync(0xffffffffu, mx0, 1));
        mx0 = fmaxf(mx0, __shfl_xor_sync(0xffffffffu, mx0, 2));
        mx1 = fmaxf(mx1, __shfl_xor_sync(0xffffffffu, mx1, 1));
        mx1 = fmaxf(mx1, __shfl_xor_sync(0xffffffffu, mx1, 2));
        const float mn0 = fmaxf(rm0, mx0), mn1 = fmaxf(rm1, mx1);
        const float f0 = __expf(rm0 - mn0), f1 = __expf(rm1 - mn1);

        float s0 = 0.0f, s1 = 0.0f;
#pragma unroll
        for (int nt = 0; nt < 16; nt++) {
            float p0 = __expf(sacc[nt][0] - mn0);
            float p1 = __expf(sacc[nt][1] - mn0);
            float p2 = __expf(sacc[nt][2] - mn1);
            float p3 = __expf(sacc[nt][3] - mn1);
            sacc[nt][0] = p0; sacc[nt][1] = p1; sacc[nt][2] = p2; sacc[nt][3] = p3;
            s0 += p0 + p1; s1 += p2 + p3;
        }
        s0 += __shfl_xor_sync(0xffffffffu, s0, 1);
        s0 += __shfl_xor_sync(0xffffffffu, s0, 2);
        s1 += __shfl_xor_sync(0xffffffffu, s1, 1);
        s1 += __shfl_xor_sync(0xffffffffu, s1, 2);
        rl0 = rl0 * f0 + s0; rl1 = rl1 * f1 + s1;
        rm0 = mn0; rm1 = mn1;

#pragma unroll
        for (int i = 0; i < 8; i++) {
            oacc[i][0] *= f0; oacc[i][1] *= f0;
            oacc[i][2] *= f1; oacc[i][3] *= f1;
        }

        // ---- O += P @ V (P fp16-converted in-register) ----
#pragma unroll
        for (int ks2 = 0; ks2 < 8; ks2++) {
            uint32_t aph[4];
            float* p0 = sacc[2 * ks2];
            float* p1 = sacc[2 * ks2 + 1];
            aph[0] = pack16(p0[0], p0[1]);
            aph[1] = pack16(p0[2], p0[3]);
            aph[2] = pack16(p1[0], p1[1]);
            aph[3] = pack16(p1[2], p1[3]);

            const uint32_t kro = ks2 * (16 * AROW);
#pragma unroll
            for (int dv = 0; dv < 4; dv++) {
                uint32_t vhf[4];
                uint32_t va = st + 1 * ATILE + v_lane + kro + dv * 32;
                LDMX4T(vhf[0], vhf[1], vhf[2], vhf[3], va);
                mma_f16(oacc[dv * 2],     aph, &vhf[0]);
                mma_f16(oacc[dv * 2 + 1], aph, &vhf[2]);
            }
        }
        __syncthreads();
    }

    // ---- normalize, store fp16 merged-head layout ----
    const float i0 = 1.0f / rl0, i1 = 1.0f / rl1;
    const size_t grow0 = (size_t)(b * S_LEN + row0) * EMB;
#pragma unroll
    for (int nt8 = 0; nt8 < 8; nt8++) {
        int col = h * HD + nt8 * 8 + (l & 3) * 2;
        *(uint32_t*)(O16 + grow0 + col) =
            pack16(oacc[nt8][0] * i0, oacc[nt8][1] * i0);
        *(uint32_t*)(O16 + grow0 + 8 * EMB + col) =
            pack16(oacc[nt8][2] * i1, oacc[nt8][3] * i1);
    }
}

// ---------------------------------------------------------------------------
// Launch
// ---------------------------------------------------------------------------
extern "C" void kernel_launch(void* const* d_in, const int* in_sizes, int n_in,
                              void* d_out, int out_size)
{
    const float* x      = (const float*)d_in[0];
    const float* w_attn = (const float*)d_in[1];
    const float* b_attn = (const float*)d_in[2];
    const float* w_proj = (const float*)d_in[3];
    const float* b_proj = (const float*)d_in[4];
    float* out = (float*)d_out;

    ush *xh, *wa, *wp, *at, *qh, *kh, *vh;
    cudaGetSymbolAddress((void**)&xh, g_xh);
    cudaGetSymbolAddress((void**)&wa, g_wa);
    cudaGetSymbolAddress((void**)&wp, g_wp);
    cudaGetSymbolAddress((void**)&at, g_at);
    cudaGetSymbolAddress((void**)&qh, g_qh);
    cudaGetSymbolAddress((void**)&kh, g_kh);
    cudaGetSymbolAddress((void**)&vh, g_vh);

    cudaFuncSetAttribute(gemm_f16,
                         cudaFuncAttributeMaxDynamicSharedMemorySize, GEMM_SMEM);
    cudaFuncSetAttribute(gemm_qkv_split,
                         cudaFuncAttributeMaxDynamicSharedMemorySize, GEMM_SMEM);
    cudaFuncSetAttribute(attn_mma,
                         cudaFuncAttributeMaxDynamicSharedMemorySize, ATT_SMEM);

    // 1) convert inputs/weights to fp16 (weights transposed to [N][K])
    {
        int n = MTOT * EMB;
        convert_x<<<(n + 255) / 256, 256>>>(x, xh, n);
        convert_transpose<<<dim3((3 * EMB) / 32, EMB / 32), dim3(32, 8)>>>(w_attn, wa, EMB, 3 * EMB);
        convert_transpose<<<dim3(EMB / 32, EMB / 32), dim3(32, 8)>>>(w_proj, wp, EMB, EMB);
    }

    // 2) QKV projection with fused per-head epilogue
    {
        dim3 grid((3 * EMB) / 128, MTOT / 128);
        gemm_qkv_split<<<grid, 256, GEMM_SMEM>>>(xh, wa, b_attn);
    }

    // 3) attention (tensor-core flash, plain fp16, 2 CTAs/SM)
    {
        dim3 grid(S_LEN / 128, HEADS, BATCH);
        attn_mma<<<grid, 256, ATT_SMEM>>>(qh, kh, vh, at);
    }

    // 4) output projection
    {
        dim3 grid(EMB / 128, MTOT / 128);
        gemm_f16<<<grid, 256, GEMM_SMEM>>>(at, wp, b_proj, out, MTOT, EMB, EMB);
    }
}